// round 1
// baseline (speedup 1.0000x reference)
#include <cuda_runtime.h>
#include <math.h>

#define C_EMBD 1024
#define NH     16
#define HD     64
#define TSEQ   2048
#define BATCH  4

// Scratch: qkv activations [B*T, 3C] and pre-projection y [B*T, C].
__device__ float g_qkv[(size_t)BATCH * TSEQ * 3 * C_EMBD];
__device__ float g_y[(size_t)BATCH * TSEQ * C_EMBD];

// ---------------------------------------------------------------------------
// Tiled SGEMM with bias: C[M,N] = A[M,K] @ B[K,N] + bias[N]
// 64x64 block tile, BK=16, 256 threads, 4x4 micro-tile per thread.
// ---------------------------------------------------------------------------
__global__ __launch_bounds__(256)
void sgemm_bias_kernel(const float* __restrict__ A,
                       const float* __restrict__ B,
                       const float* __restrict__ bias,
                       float* __restrict__ Cm,
                       int M, int N, int K)
{
    constexpr int BM = 64, BN = 64, BK = 16;
    __shared__ float As[BK][BM];   // K-major A tile (transposed on load)
    __shared__ float Bs[BK][BN];   // natural B tile

    const int tid = threadIdx.x;
    const int tx = tid & 15;
    const int ty = tid >> 4;
    const int bm0 = blockIdx.y * BM;
    const int bn0 = blockIdx.x * BN;

    float acc[4][4] = {};

    for (int k0 = 0; k0 < K; k0 += BK) {
        // Load A tile (64 rows x 16 cols), one float4 per thread, scatter to K-major.
        {
            int r  = tid >> 2;            // 0..63
            int c4 = (tid & 3) * 4;       // 0,4,8,12
            float4 a = *(const float4*)&A[(size_t)(bm0 + r) * K + k0 + c4];
            As[c4 + 0][r] = a.x;
            As[c4 + 1][r] = a.y;
            As[c4 + 2][r] = a.z;
            As[c4 + 3][r] = a.w;
        }
        // Load B tile (16 rows x 64 cols), one float4 per thread.
        {
            int kk = tid >> 4;            // 0..15
            int c4 = (tid & 15) * 4;      // 0..60
            *(float4*)&Bs[kk][c4] = *(const float4*)&B[(size_t)(k0 + kk) * N + bn0 + c4];
        }
        __syncthreads();

        #pragma unroll
        for (int kk = 0; kk < BK; kk++) {
            float4 a4 = *(const float4*)&As[kk][ty * 4];
            float4 b4 = *(const float4*)&Bs[kk][tx * 4];
            float av[4] = {a4.x, a4.y, a4.z, a4.w};
            float bv[4] = {b4.x, b4.y, b4.z, b4.w};
            #pragma unroll
            for (int i = 0; i < 4; i++)
                #pragma unroll
                for (int j = 0; j < 4; j++)
                    acc[i][j] = fmaf(av[i], bv[j], acc[i][j]);
        }
        __syncthreads();
    }

    #pragma unroll
    for (int i = 0; i < 4; i++) {
        int r = bm0 + ty * 4 + i;
        int c = bn0 + tx * 4;
        float4 o;
        o.x = acc[i][0] + bias[c + 0];
        o.y = acc[i][1] + bias[c + 1];
        o.z = acc[i][2] + bias[c + 2];
        o.w = acc[i][3] + bias[c + 3];
        *(float4*)&Cm[(size_t)r * N + c] = o;
    }
}

// ---------------------------------------------------------------------------
// Fused causal attention (flash-attention style), fp32.
// One block per (q-tile of 64 rows, head, batch). 256 threads, 4x4 micro-tiles.
// Online softmax; tiles strictly above the diagonal are skipped.
// ---------------------------------------------------------------------------
__global__ __launch_bounds__(256)
void attn_kernel(const float* __restrict__ qkv, float* __restrict__ y)
{
    extern __shared__ float sm[];
    constexpr int LD = 65;           // padded leading dim (bank-conflict relief)
    float* Qs = sm;                  // [64][65]
    float* Ks = Qs + 64 * LD;        // [64][65]
    float* Vs = Ks + 64 * LD;        // [64][65]
    float* Ps = Vs + 64 * LD;        // [64][65]

    const int tid = threadIdx.x;
    const int tx = tid & 15;
    const int ty = tid >> 4;
    const int itile = blockIdx.x;    // q tile index (0..31)
    const int h = blockIdx.y;
    const int b = blockIdx.z;

    const float* base = qkv + (size_t)b * TSEQ * (3 * C_EMBD) + h * HD;

    // Load Q tile [64][64] (cols 0..C-1 of qkv rows)
    for (int e = tid; e < 64 * 64; e += 256) {
        int r = e >> 6, d = e & 63;
        Qs[r * LD + d] = base[(size_t)(itile * 64 + r) * (3 * C_EMBD) + d];
    }

    float m[4], l[4], o[4][4];
    #pragma unroll
    for (int i = 0; i < 4; i++) {
        m[i] = -INFINITY;
        l[i] = 0.f;
        #pragma unroll
        for (int j = 0; j < 4; j++) o[i][j] = 0.f;
    }

    const float scale = 0.125f;  // 1/sqrt(64)

    for (int jt = 0; jt <= itile; jt++) {
        __syncthreads();  // previous iteration done with Ks/Vs/Ps (also covers Qs load)
        // Load K and V tiles
        for (int e = tid; e < 64 * 64; e += 256) {
            int r = e >> 6, d = e & 63;
            size_t row = (size_t)(jt * 64 + r) * (3 * C_EMBD);
            Ks[r * LD + d] = base[row + C_EMBD + d];
            Vs[r * LD + d] = base[row + 2 * C_EMBD + d];
        }
        __syncthreads();

        // S = scale * Q @ K^T
        float s[4][4] = {};
        #pragma unroll 8
        for (int d = 0; d < 64; d++) {
            float qv[4], kv[4];
            #pragma unroll
            for (int i = 0; i < 4; i++) qv[i] = Qs[(ty * 4 + i) * LD + d];
            #pragma unroll
            for (int j = 0; j < 4; j++) kv[j] = Ks[(tx * 4 + j) * LD + d];
            #pragma unroll
            for (int i = 0; i < 4; i++)
                #pragma unroll
                for (int j = 0; j < 4; j++)
                    s[i][j] = fmaf(qv[i], kv[j], s[i][j]);
        }

        #pragma unroll
        for (int i = 0; i < 4; i++)
            #pragma unroll
            for (int j = 0; j < 4; j++)
                s[i][j] *= scale;

        if (jt == itile) {  // causal mask on diagonal tile
            #pragma unroll
            for (int i = 0; i < 4; i++) {
                int r = ty * 4 + i;
                #pragma unroll
                for (int j = 0; j < 4; j++) {
                    int c = tx * 4 + j;
                    if (c > r) s[i][j] = -INFINITY;
                }
            }
        }

        // Online softmax update
        #pragma unroll
        for (int i = 0; i < 4; i++) {
            float v = fmaxf(fmaxf(s[i][0], s[i][1]), fmaxf(s[i][2], s[i][3]));
            #pragma unroll
            for (int off = 8; off >= 1; off >>= 1)
                v = fmaxf(v, __shfl_xor_sync(0xffffffffu, v, off));
            float mn = fmaxf(m[i], v);
            float alpha = __expf(m[i] - mn);
            float rs = 0.f;
            #pragma unroll
            for (int j = 0; j < 4; j++) {
                float p = __expf(s[i][j] - mn);
                s[i][j] = p;
                rs += p;
            }
            #pragma unroll
            for (int off = 8; off >= 1; off >>= 1)
                rs += __shfl_xor_sync(0xffffffffu, rs, off);
            l[i] = l[i] * alpha + rs;
            m[i] = mn;
            #pragma unroll
            for (int j = 0; j < 4; j++) o[i][j] *= alpha;
        }

        // Stage P tile to smem
        #pragma unroll
        for (int i = 0; i < 4; i++)
            #pragma unroll
            for (int j = 0; j < 4; j++)
                Ps[(ty * 4 + i) * LD + (tx * 4 + j)] = s[i][j];
        __syncthreads();

        // O += P @ V
        #pragma unroll 8
        for (int c = 0; c < 64; c++) {
            float pv[4], vv[4];
            #pragma unroll
            for (int i = 0; i < 4; i++) pv[i] = Ps[(ty * 4 + i) * LD + c];
            #pragma unroll
            for (int j = 0; j < 4; j++) vv[j] = Vs[c * LD + tx * 4 + j];
            #pragma unroll
            for (int i = 0; i < 4; i++)
                #pragma unroll
                for (int j = 0; j < 4; j++)
                    o[i][j] = fmaf(pv[i], vv[j], o[i][j]);
        }
    }

    // Write y = O / l
    float* yb = y + (size_t)b * TSEQ * C_EMBD + h * HD;
    #pragma unroll
    for (int i = 0; i < 4; i++) {
        float inv = 1.f / l[i];
        int r = itile * 64 + ty * 4 + i;
        int d = tx * 4;
        float4 ov;
        ov.x = o[i][0] * inv;
        ov.y = o[i][1] * inv;
        ov.z = o[i][2] * inv;
        ov.w = o[i][3] * inv;
        *(float4*)&yb[(size_t)r * C_EMBD + d] = ov;
    }
}

// ---------------------------------------------------------------------------
extern "C" void kernel_launch(void* const* d_in, const int* in_sizes, int n_in,
                              void* d_out, int out_size)
{
    const float* x      = (const float*)d_in[0];   // [4,2048,1024]
    const float* W_attn = (const float*)d_in[1];   // [1024,3072]
    const float* b_attn = (const float*)d_in[2];   // [3072]
    const float* W_proj = (const float*)d_in[3];   // [1024,1024]
    const float* b_proj = (const float*)d_in[4];   // [1024]
    float* out = (float*)d_out;                    // [4,2048,1024]

    float *qkv, *y;
    cudaGetSymbolAddress((void**)&qkv, g_qkv);
    cudaGetSymbolAddress((void**)&y, g_y);

    const int M = BATCH * TSEQ;  // 8192

    // 1) QKV GEMM: [8192,1024] @ [1024,3072] + b_attn
    {
        dim3 grid(3 * C_EMBD / 64, M / 64);
        sgemm_bias_kernel<<<grid, 256>>>(x, W_attn, b_attn, qkv, M, 3 * C_EMBD, C_EMBD);
    }

    // 2) Fused causal attention -> y
    {
        static int smem_set = 0;
        const int smem_bytes = 4 * 64 * 65 * (int)sizeof(float);  // 66560
        if (!smem_set) {
            cudaFuncSetAttribute(attn_kernel,
                                 cudaFuncAttributeMaxDynamicSharedMemorySize,
                                 smem_bytes);
            smem_set = 1;
        }
        dim3 grid(TSEQ / 64, NH, BATCH);
        attn_kernel<<<grid, 256, smem_bytes>>>(qkv, y);
    }

    // 3) Output projection: [8192,1024] @ [1024,1024] + b_proj
    {
        dim3 grid(C_EMBD / 64, M / 64);
        sgemm_bias_kernel<<<grid, 256>>>(y, W_proj, b_proj, out, M, C_EMBD, C_EMBD);
    }
}

// round 3
// speedup vs baseline: 1.7924x; 1.7924x over previous
#include <cuda_runtime.h>
#include <cstdint>
#include <math.h>

#define C_EMBD 1024
#define NH     16
#define HD     64
#define TSEQ   2048
#define BATCH  4

// Scratch: qkv activations [B*T, 3C], pre-projection y [B*T, C],
// and pre-transposed weights W_attn^T [3C, C], W_proj^T [C, C].
__device__ float g_qkv[(size_t)BATCH * TSEQ * 3 * C_EMBD];
__device__ float g_y[(size_t)BATCH * TSEQ * C_EMBD];
__device__ float g_WaT[(size_t)3 * C_EMBD * C_EMBD];
__device__ float g_WpT[(size_t)C_EMBD * C_EMBD];

// ---------------------------------------------------------------------------
// Helpers
// ---------------------------------------------------------------------------
__device__ __forceinline__ uint32_t smem_u32(const void* p) {
    uint32_t a;
    asm("{ .reg .u64 t; cvta.to.shared.u64 t, %1; cvt.u32.u64 %0, t; }" : "=r"(a) : "l"(p));
    return a;
}
__device__ __forceinline__ void cp_async16(uint32_t dst, const void* src) {
    asm volatile("cp.async.cg.shared.global [%0], [%1], 16;" :: "r"(dst), "l"(src) : "memory");
}
__device__ __forceinline__ void cp_commit() {
    asm volatile("cp.async.commit_group;" ::: "memory");
}
template <int N>
__device__ __forceinline__ void cp_wait() {
    asm volatile("cp.async.wait_group %0;" :: "n"(N) : "memory");
}
__device__ __forceinline__ uint32_t f2tf32(float x) {
    uint32_t y;
    asm("cvt.rna.tf32.f32 %0, %1;" : "=r"(y) : "f"(x));
    return y;
}
__device__ __forceinline__ void mma_tf32(float* c, uint32_t a0, uint32_t a1,
                                         uint32_t a2, uint32_t a3,
                                         uint32_t b0, uint32_t b1) {
    asm volatile(
        "mma.sync.aligned.m16n8k8.row.col.f32.tf32.tf32.f32 "
        "{%0,%1,%2,%3}, {%4,%5,%6,%7}, {%8,%9}, {%0,%1,%2,%3};"
        : "+f"(c[0]), "+f"(c[1]), "+f"(c[2]), "+f"(c[3])
        : "r"(a0), "r"(a1), "r"(a2), "r"(a3), "r"(b0), "r"(b1));
}

// Chunk-rotated smem layout for a [128][32]-float tile:
// element (row, k) lives at float index row*32 + ((k/4 + row)%8)*4 + (k%4).
// Fragment loads (scalar LDS) are bank-conflict-free; float4 stores hit the
// 4-phase floor.
__device__ __forceinline__ int tile_idx(int row, int k) {
    return row * 32 + ((((k >> 2) + row) & 7) << 2) + (k & 3);
}

// ---------------------------------------------------------------------------
// Weight transpose: W[R][Ncols] -> WT[Ncols][R]
// ---------------------------------------------------------------------------
__global__ __launch_bounds__(256)
void transpose_kernel(const float* __restrict__ W, float* __restrict__ WT,
                      int R, int Ncols)
{
    __shared__ float t[32][33];
    const int bx = blockIdx.x * 32;
    const int by = blockIdx.y * 32;
    const int tx = threadIdx.x & 31;
    const int ty8 = threadIdx.x >> 5;
    #pragma unroll
    for (int i = 0; i < 32; i += 8)
        t[ty8 + i][tx] = W[(size_t)(by + ty8 + i) * Ncols + bx + tx];
    __syncthreads();
    #pragma unroll
    for (int i = 0; i < 32; i += 8)
        WT[(size_t)(bx + ty8 + i) * R + by + tx] = t[tx][ty8 + i];
}

// ---------------------------------------------------------------------------
// tf32 mma.sync GEMM with bias: C[M,N] = A[M,K] @ BT[N,K]^T + bias[N]
// CTA tile 128x128, BK=32, 256 threads (8 warps, 2x4), warp tile 64x32.
// Double-buffered cp.async pipeline.
// ---------------------------------------------------------------------------
// dyn smem: A0 @0, A1 @16384, B0 @32768, B1 @49152  (total 65536)
#define GEMM_SMEM 65536

__global__ __launch_bounds__(256, 1)
void tf32_gemm_kernel(const float* __restrict__ A,
                      const float* __restrict__ BT,
                      const float* __restrict__ bias,
                      float* __restrict__ Cm,
                      int M, int N, int K)
{
    extern __shared__ char smem[];
    const uint32_t sb = smem_u32(smem);
    float* const Sf = (float*)smem;

    const int tid = threadIdx.x;
    const int wid = tid >> 5;
    const int lane = tid & 31;
    const int g = lane >> 2;      // groupID 0..7
    const int t = lane & 3;       // threadID_in_group 0..3
    const int wm = wid >> 2;      // 0..1  (warp m index)
    const int wn = wid & 3;       // 0..3  (warp n index)

    const int bm0 = blockIdx.y * 128;
    const int bn0 = blockIdx.x * 128;
    const int NS = K >> 5;        // stages of BK=32

    float acc[4][4][4];
    #pragma unroll
    for (int i = 0; i < 4; i++)
        #pragma unroll
        for (int j = 0; j < 4; j++)
            #pragma unroll
            for (int r = 0; r < 4; r++) acc[i][j][r] = 0.f;

    // Per-thread global load coordinates: 4 float4 per tile per thread.
    // idx = it*256 + tid; local row = idx>>3 (0..127); chunk = idx&7.
    auto load_stage = [&](int s) {
        const int k0 = s * 32;
        const uint32_t sA = sb + (s & 1) * 16384;
        const uint32_t sB = sb + 32768 + (s & 1) * 16384;
        #pragma unroll
        for (int it = 0; it < 4; it++) {
            int idx = it * 256 + tid;
            int r = idx >> 3, ck = idx & 7;
            uint32_t d = sA + r * 128 + ((((ck + r) & 7)) << 4);
            cp_async16(d, &A[(size_t)(bm0 + r) * K + k0 + ck * 4]);
        }
        #pragma unroll
        for (int it = 0; it < 4; it++) {
            int idx = it * 256 + tid;
            int r = idx >> 3, ck = idx & 7;
            uint32_t d = sB + r * 128 + ((((ck + r) & 7)) << 4);
            cp_async16(d, &BT[(size_t)(bn0 + r) * K + k0 + ck * 4]);
        }
        cp_commit();
    };

    load_stage(0);

    for (int s = 0; s < NS; s++) {
        if (s + 1 < NS) {
            load_stage(s + 1);
            cp_wait<1>();
        } else {
            cp_wait<0>();
        }
        __syncthreads();

        const float* As = Sf + ((s & 1) ? 4096 : 0);
        const float* Bs = Sf + 8192 + ((s & 1) ? 4096 : 0);

        #pragma unroll
        for (int ks = 0; ks < 4; ks++) {
            const int kb = ks * 8;
            uint32_t afr[4][4];
            #pragma unroll
            for (int mi = 0; mi < 4; mi++) {
                int m = wm * 64 + mi * 16 + g;
                afr[mi][0] = f2tf32(As[tile_idx(m,     kb + t)]);
                afr[mi][1] = f2tf32(As[tile_idx(m + 8, kb + t)]);
                afr[mi][2] = f2tf32(As[tile_idx(m,     kb + t + 4)]);
                afr[mi][3] = f2tf32(As[tile_idx(m + 8, kb + t + 4)]);
            }
            uint32_t bfr[4][2];
            #pragma unroll
            for (int ni = 0; ni < 4; ni++) {
                int n = wn * 32 + ni * 8 + g;
                bfr[ni][0] = f2tf32(Bs[tile_idx(n, kb + t)]);
                bfr[ni][1] = f2tf32(Bs[tile_idx(n, kb + t + 4)]);
            }
            #pragma unroll
            for (int mi = 0; mi < 4; mi++)
                #pragma unroll
                for (int ni = 0; ni < 4; ni++)
                    mma_tf32(acc[mi][ni],
                             afr[mi][0], afr[mi][1], afr[mi][2], afr[mi][3],
                             bfr[ni][0], bfr[ni][1]);
        }
        __syncthreads();
    }

    // Epilogue: c0 (row g, col 2t), c1 (row g, col 2t+1), c2/c3 (row g+8).
    #pragma unroll
    for (int mi = 0; mi < 4; mi++) {
        #pragma unroll
        for (int ni = 0; ni < 4; ni++) {
            int row0 = bm0 + wm * 64 + mi * 16 + g;
            int col  = bn0 + wn * 32 + ni * 8 + 2 * t;
            float bx = bias[col], by = bias[col + 1];
            float2 v0 = {acc[mi][ni][0] + bx, acc[mi][ni][1] + by};
            float2 v1 = {acc[mi][ni][2] + bx, acc[mi][ni][3] + by};
            *(float2*)&Cm[(size_t)row0 * N + col] = v0;
            *(float2*)&Cm[(size_t)(row0 + 8) * N + col] = v1;
        }
    }
}

// ---------------------------------------------------------------------------
// Fused causal attention (flash-attention style), fp32. (unchanged from R1)
// ---------------------------------------------------------------------------
__global__ __launch_bounds__(256)
void attn_kernel(const float* __restrict__ qkv, float* __restrict__ y)
{
    extern __shared__ float sm[];
    constexpr int LD = 65;
    float* Qs = sm;
    float* Ks = Qs + 64 * LD;
    float* Vs = Ks + 64 * LD;
    float* Ps = Vs + 64 * LD;

    const int tid = threadIdx.x;
    const int tx = tid & 15;
    const int ty = tid >> 4;
    const int itile = blockIdx.x;
    const int h = blockIdx.y;
    const int b = blockIdx.z;

    const float* base = qkv + (size_t)b * TSEQ * (3 * C_EMBD) + h * HD;

    for (int e = tid; e < 64 * 64; e += 256) {
        int r = e >> 6, d = e & 63;
        Qs[r * LD + d] = base[(size_t)(itile * 64 + r) * (3 * C_EMBD) + d];
    }

    float m[4], l[4], o[4][4];
    #pragma unroll
    for (int i = 0; i < 4; i++) {
        m[i] = -INFINITY;
        l[i] = 0.f;
        #pragma unroll
        for (int j = 0; j < 4; j++) o[i][j] = 0.f;
    }

    const float scale = 0.125f;

    for (int jt = 0; jt <= itile; jt++) {
        __syncthreads();
        for (int e = tid; e < 64 * 64; e += 256) {
            int r = e >> 6, d = e & 63;
            size_t row = (size_t)(jt * 64 + r) * (3 * C_EMBD);
            Ks[r * LD + d] = base[row + C_EMBD + d];
            Vs[r * LD + d] = base[row + 2 * C_EMBD + d];
        }
        __syncthreads();

        float s[4][4] = {};
        #pragma unroll 8
        for (int d = 0; d < 64; d++) {
            float qv[4], kv[4];
            #pragma unroll
            for (int i = 0; i < 4; i++) qv[i] = Qs[(ty * 4 + i) * LD + d];
            #pragma unroll
            for (int j = 0; j < 4; j++) kv[j] = Ks[(tx * 4 + j) * LD + d];
            #pragma unroll
            for (int i = 0; i < 4; i++)
                #pragma unroll
                for (int j = 0; j < 4; j++)
                    s[i][j] = fmaf(qv[i], kv[j], s[i][j]);
        }

        #pragma unroll
        for (int i = 0; i < 4; i++)
            #pragma unroll
            for (int j = 0; j < 4; j++)
                s[i][j] *= scale;

        if (jt == itile) {
            #pragma unroll
            for (int i = 0; i < 4; i++) {
                int r = ty * 4 + i;
                #pragma unroll
                for (int j = 0; j < 4; j++) {
                    int c = tx * 4 + j;
                    if (c > r) s[i][j] = -INFINITY;
                }
            }
        }

        #pragma unroll
        for (int i = 0; i < 4; i++) {
            float v = fmaxf(fmaxf(s[i][0], s[i][1]), fmaxf(s[i][2], s[i][3]));
            #pragma unroll
            for (int off = 8; off >= 1; off >>= 1)
                v = fmaxf(v, __shfl_xor_sync(0xffffffffu, v, off));
            float mn = fmaxf(m[i], v);
            float alpha = __expf(m[i] - mn);
            float rs = 0.f;
            #pragma unroll
            for (int j = 0; j < 4; j++) {
                float p = __expf(s[i][j] - mn);
                s[i][j] = p;
                rs += p;
            }
            #pragma unroll
            for (int off = 8; off >= 1; off >>= 1)
                rs += __shfl_xor_sync(0xffffffffu, rs, off);
            l[i] = l[i] * alpha + rs;
            m[i] = mn;
            #pragma unroll
            for (int j = 0; j < 4; j++) o[i][j] *= alpha;
        }

        #pragma unroll
        for (int i = 0; i < 4; i++)
            #pragma unroll
            for (int j = 0; j < 4; j++)
                Ps[(ty * 4 + i) * LD + (tx * 4 + j)] = s[i][j];
        __syncthreads();

        #pragma unroll 8
        for (int c = 0; c < 64; c++) {
            float pv[4], vv[4];
            #pragma unroll
            for (int i = 0; i < 4; i++) pv[i] = Ps[(ty * 4 + i) * LD + c];
            #pragma unroll
            for (int j = 0; j < 4; j++) vv[j] = Vs[c * LD + tx * 4 + j];
            #pragma unroll
            for (int i = 0; i < 4; i++)
                #pragma unroll
                for (int j = 0; j < 4; j++)
                    o[i][j] = fmaf(pv[i], vv[j], o[i][j]);
        }
    }

    float* yb = y + (size_t)b * TSEQ * C_EMBD + h * HD;
    #pragma unroll
    for (int i = 0; i < 4; i++) {
        float inv = 1.f / l[i];
        int r = itile * 64 + ty * 4 + i;
        int d = tx * 4;
        float4 ov;
        ov.x = o[i][0] * inv;
        ov.y = o[i][1] * inv;
        ov.z = o[i][2] * inv;
        ov.w = o[i][3] * inv;
        *(float4*)&yb[(size_t)r * C_EMBD + d] = ov;
    }
}

// ---------------------------------------------------------------------------
extern "C" void kernel_launch(void* const* d_in, const int* in_sizes, int n_in,
                              void* d_out, int out_size)
{
    const float* x      = (const float*)d_in[0];   // [4,2048,1024]
    const float* W_attn = (const float*)d_in[1];   // [1024,3072]
    const float* b_attn = (const float*)d_in[2];   // [3072]
    const float* W_proj = (const float*)d_in[3];   // [1024,1024]
    const float* b_proj = (const float*)d_in[4];   // [1024]
    float* out = (float*)d_out;                    // [4,2048,1024]

    float *qkv, *y, *WaT, *WpT;
    cudaGetSymbolAddress((void**)&qkv, g_qkv);
    cudaGetSymbolAddress((void**)&y, g_y);
    cudaGetSymbolAddress((void**)&WaT, g_WaT);
    cudaGetSymbolAddress((void**)&WpT, g_WpT);

    const int M = BATCH * TSEQ;  // 8192

    static int attr_set = 0;
    if (!attr_set) {
        cudaFuncSetAttribute(tf32_gemm_kernel,
                             cudaFuncAttributeMaxDynamicSharedMemorySize, GEMM_SMEM);
        cudaFuncSetAttribute(attn_kernel,
                             cudaFuncAttributeMaxDynamicSharedMemorySize,
                             4 * 64 * 65 * (int)sizeof(float));
        attr_set = 1;
    }

    // 0) Pre-transpose weights: W[K,N] -> WT[N,K]
    {
        dim3 g1(3 * C_EMBD / 32, C_EMBD / 32);
        transpose_kernel<<<g1, 256>>>(W_attn, WaT, C_EMBD, 3 * C_EMBD);
        dim3 g2(C_EMBD / 32, C_EMBD / 32);
        transpose_kernel<<<g2, 256>>>(W_proj, WpT, C_EMBD, C_EMBD);
    }

    // 1) QKV GEMM (mma.sync tf32): [8192,1024] @ [1024,3072] + b_attn
    {
        dim3 grid(3 * C_EMBD / 128, M / 128);
        tf32_gemm_kernel<<<grid, 256, GEMM_SMEM>>>(x, WaT, b_attn, qkv,
                                                   M, 3 * C_EMBD, C_EMBD);
    }

    // 2) Fused causal attention -> y (fp32 CUDA cores)
    {
        const int smem_bytes = 4 * 64 * 65 * (int)sizeof(float);
        dim3 grid(TSEQ / 64, NH, BATCH);
        attn_kernel<<<grid, 256, smem_bytes>>>(qkv, y);
    }

    // 3) Output projection (mma.sync tf32): [8192,1024] @ [1024,1024] + b_proj
    {
        dim3 grid(C_EMBD / 128, M / 128);
        tf32_gemm_kernel<<<grid, 256, GEMM_SMEM>>>(y, WpT, b_proj, out,
                                                   M, C_EMBD, C_EMBD);
    }
}

// round 4
// speedup vs baseline: 3.6692x; 2.0471x over previous
#include <cuda_runtime.h>
#include <cstdint>
#include <math.h>

#define C_EMBD 1024
#define NH     16
#define HD     64
#define TSEQ   2048
#define BATCH  4

__device__ float g_qkv[(size_t)BATCH * TSEQ * 3 * C_EMBD];
__device__ float g_y[(size_t)BATCH * TSEQ * C_EMBD];
__device__ float g_WaT[(size_t)3 * C_EMBD * C_EMBD];
__device__ float g_WpT[(size_t)C_EMBD * C_EMBD];

// ---------------------------------------------------------------------------
// Helpers
// ---------------------------------------------------------------------------
__device__ __forceinline__ uint32_t smem_u32(const void* p) {
    uint32_t a;
    asm("{ .reg .u64 t; cvta.to.shared.u64 t, %1; cvt.u32.u64 %0, t; }" : "=r"(a) : "l"(p));
    return a;
}
__device__ __forceinline__ void cp_async16(uint32_t dst, const void* src) {
    asm volatile("cp.async.cg.shared.global [%0], [%1], 16;" :: "r"(dst), "l"(src) : "memory");
}
__device__ __forceinline__ void cp_commit() {
    asm volatile("cp.async.commit_group;" ::: "memory");
}
template <int N>
__device__ __forceinline__ void cp_wait() {
    asm volatile("cp.async.wait_group %0;" :: "n"(N) : "memory");
}
__device__ __forceinline__ uint32_t f2tf32(float x) {
    uint32_t y;
    asm("cvt.rna.tf32.f32 %0, %1;" : "=r"(y) : "f"(x));
    return y;
}
__device__ __forceinline__ void mma_tf32(float* c, uint32_t a0, uint32_t a1,
                                         uint32_t a2, uint32_t a3,
                                         uint32_t b0, uint32_t b1) {
    asm volatile(
        "mma.sync.aligned.m16n8k8.row.col.f32.tf32.tf32.f32 "
        "{%0,%1,%2,%3}, {%4,%5,%6,%7}, {%8,%9}, {%0,%1,%2,%3};"
        : "+f"(c[0]), "+f"(c[1]), "+f"(c[2]), "+f"(c[3])
        : "r"(a0), "r"(a1), "r"(a2), "r"(a3), "r"(b0), "r"(b1));
}
__device__ __forceinline__ int tile_idx(int row, int k) {
    return row * 32 + ((((k >> 2) + row) & 7) << 2) + (k & 3);
}

// ---------------------------------------------------------------------------
// Weight transpose: W[R][Ncols] -> WT[Ncols][R]
// ---------------------------------------------------------------------------
__global__ __launch_bounds__(256)
void transpose_kernel(const float* __restrict__ W, float* __restrict__ WT,
                      int R, int Ncols)
{
    __shared__ float t[32][33];
    const int bx = blockIdx.x * 32;
    const int by = blockIdx.y * 32;
    const int tx = threadIdx.x & 31;
    const int ty8 = threadIdx.x >> 5;
    #pragma unroll
    for (int i = 0; i < 32; i += 8)
        t[ty8 + i][tx] = W[(size_t)(by + ty8 + i) * Ncols + bx + tx];
    __syncthreads();
    #pragma unroll
    for (int i = 0; i < 32; i += 8)
        WT[(size_t)(bx + ty8 + i) * R + by + tx] = t[tx][ty8 + i];
}

// ---------------------------------------------------------------------------
// tf32 mma.sync GEMM with bias (unchanged from R3, validated)
// ---------------------------------------------------------------------------
#define GEMM_SMEM 65536

__global__ __launch_bounds__(256, 1)
void tf32_gemm_kernel(const float* __restrict__ A,
                      const float* __restrict__ BT,
                      const float* __restrict__ bias,
                      float* __restrict__ Cm,
                      int M, int N, int K)
{
    extern __shared__ char smem[];
    const uint32_t sb = smem_u32(smem);
    float* const Sf = (float*)smem;

    const int tid = threadIdx.x;
    const int wid = tid >> 5;
    const int lane = tid & 31;
    const int g = lane >> 2;
    const int t = lane & 3;
    const int wm = wid >> 2;
    const int wn = wid & 3;

    const int bm0 = blockIdx.y * 128;
    const int bn0 = blockIdx.x * 128;
    const int NS = K >> 5;

    float acc[4][4][4];
    #pragma unroll
    for (int i = 0; i < 4; i++)
        #pragma unroll
        for (int j = 0; j < 4; j++)
            #pragma unroll
            for (int r = 0; r < 4; r++) acc[i][j][r] = 0.f;

    auto load_stage = [&](int s) {
        const int k0 = s * 32;
        const uint32_t sA = sb + (s & 1) * 16384;
        const uint32_t sB = sb + 32768 + (s & 1) * 16384;
        #pragma unroll
        for (int it = 0; it < 4; it++) {
            int idx = it * 256 + tid;
            int r = idx >> 3, ck = idx & 7;
            uint32_t d = sA + r * 128 + ((((ck + r) & 7)) << 4);
            cp_async16(d, &A[(size_t)(bm0 + r) * K + k0 + ck * 4]);
        }
        #pragma unroll
        for (int it = 0; it < 4; it++) {
            int idx = it * 256 + tid;
            int r = idx >> 3, ck = idx & 7;
            uint32_t d = sB + r * 128 + ((((ck + r) & 7)) << 4);
            cp_async16(d, &BT[(size_t)(bn0 + r) * K + k0 + ck * 4]);
        }
        cp_commit();
    };

    load_stage(0);

    for (int s = 0; s < NS; s++) {
        if (s + 1 < NS) {
            load_stage(s + 1);
            cp_wait<1>();
        } else {
            cp_wait<0>();
        }
        __syncthreads();

        const float* As = Sf + ((s & 1) ? 4096 : 0);
        const float* Bs = Sf + 8192 + ((s & 1) ? 4096 : 0);

        #pragma unroll
        for (int ks = 0; ks < 4; ks++) {
            const int kb = ks * 8;
            uint32_t afr[4][4];
            #pragma unroll
            for (int mi = 0; mi < 4; mi++) {
                int m = wm * 64 + mi * 16 + g;
                afr[mi][0] = f2tf32(As[tile_idx(m,     kb + t)]);
                afr[mi][1] = f2tf32(As[tile_idx(m + 8, kb + t)]);
                afr[mi][2] = f2tf32(As[tile_idx(m,     kb + t + 4)]);
                afr[mi][3] = f2tf32(As[tile_idx(m + 8, kb + t + 4)]);
            }
            uint32_t bfr[4][2];
            #pragma unroll
            for (int ni = 0; ni < 4; ni++) {
                int n = wn * 32 + ni * 8 + g;
                bfr[ni][0] = f2tf32(Bs[tile_idx(n, kb + t)]);
                bfr[ni][1] = f2tf32(Bs[tile_idx(n, kb + t + 4)]);
            }
            #pragma unroll
            for (int mi = 0; mi < 4; mi++)
                #pragma unroll
                for (int ni = 0; ni < 4; ni++)
                    mma_tf32(acc[mi][ni],
                             afr[mi][0], afr[mi][1], afr[mi][2], afr[mi][3],
                             bfr[ni][0], bfr[ni][1]);
        }
        __syncthreads();
    }

    #pragma unroll
    for (int mi = 0; mi < 4; mi++) {
        #pragma unroll
        for (int ni = 0; ni < 4; ni++) {
            int row0 = bm0 + wm * 64 + mi * 16 + g;
            int col  = bn0 + wn * 32 + ni * 8 + 2 * t;
            float bx = bias[col], by = bias[col + 1];
            float2 v0 = {acc[mi][ni][0] + bx, acc[mi][ni][1] + by};
            float2 v1 = {acc[mi][ni][2] + bx, acc[mi][ni][3] + by};
            *(float2*)&Cm[(size_t)row0 * N + col] = v0;
            *(float2*)&Cm[(size_t)(row0 + 8) * N + col] = v1;
        }
    }
}

// ---------------------------------------------------------------------------
// Tensor-core flash attention (tf32 mma.sync), causal.
// Block: 128 Q rows x 1 head. 4 warps, each 32 rows (2 m16 tiles). KV tile 64.
// smem (u32): Qs[128][68] @0, Ks[64][68] @8704, Vs[64][72] @13056,
//             Ps[128][68] @17664 (per-warp 32-row slices). Total 105472 B.
// Strides: 68 -> fragment banks 4g+t (conflict-free); 72 -> 8t+g (conflict-free).
// ---------------------------------------------------------------------------
#define ATT_SMEM 105472

__global__ __launch_bounds__(128, 1)
void attn_tc_kernel(const float* __restrict__ qkv, float* __restrict__ y)
{
    extern __shared__ uint32_t smu[];
    uint32_t* const Qs = smu;
    uint32_t* const Ks = smu + 8704;
    uint32_t* const Vs = smu + 13056;
    uint32_t* const Ps = smu + 17664;

    const int tid = threadIdx.x;
    const int wid = tid >> 5;
    const int lane = tid & 31;
    const int g = lane >> 2;
    const int t = lane & 3;
    const int bx = blockIdx.x;       // 128-row Q tile index (0..15)
    const int h = blockIdx.y;
    const int b = blockIdx.z;
    const int qb = bx * 128;

    const float* base = qkv + (size_t)b * TSEQ * (3 * C_EMBD) + h * HD;

    // Stage Q tile [128][64], scaled by 1/8 and tf32-rounded.
    #pragma unroll
    for (int it = 0; it < 16; it++) {
        int idx = it * 128 + tid;            // 0..2047
        int r = idx >> 4, c4 = idx & 15;
        float4 v = *(const float4*)&base[(size_t)(qb + r) * (3 * C_EMBD) + c4 * 4];
        uint4 u;
        u.x = f2tf32(v.x * 0.125f);
        u.y = f2tf32(v.y * 0.125f);
        u.z = f2tf32(v.z * 0.125f);
        u.w = f2tf32(v.w * 0.125f);
        *(uint4*)&Qs[r * 68 + c4 * 4] = u;
    }

    float m[4], l[4], o[2][8][4];
    #pragma unroll
    for (int rm = 0; rm < 4; rm++) { m[rm] = -1e30f; l[rm] = 0.f; }
    #pragma unroll
    for (int mi = 0; mi < 2; mi++)
        #pragma unroll
        for (int ni = 0; ni < 8; ni++)
            #pragma unroll
            for (int k = 0; k < 4; k++) o[mi][ni][k] = 0.f;

    const int ntiles = 2 * bx + 2;
    for (int jt = 0; jt < ntiles; jt++) {
        __syncthreads();  // protect Ks/Vs (prev iter readers) + Qs staging (first iter)
        // Load K/V tile [64][64] each, tf32-rounded.
        #pragma unroll
        for (int it = 0; it < 8; it++) {
            int idx = it * 128 + tid;        // 0..1023
            int r = idx >> 4, c4 = idx & 15;
            const float* rp = &base[(size_t)(jt * 64 + r) * (3 * C_EMBD) + c4 * 4];
            float4 kv = *(const float4*)(rp + C_EMBD);
            float4 vv = *(const float4*)(rp + 2 * C_EMBD);
            uint4 uk, uv;
            uk.x = f2tf32(kv.x); uk.y = f2tf32(kv.y); uk.z = f2tf32(kv.z); uk.w = f2tf32(kv.w);
            uv.x = f2tf32(vv.x); uv.y = f2tf32(vv.y); uv.z = f2tf32(vv.z); uv.w = f2tf32(vv.w);
            *(uint4*)&Ks[r * 68 + c4 * 4] = uk;
            *(uint4*)&Vs[r * 72 + c4 * 4] = uv;
        }
        __syncthreads();

        // ---- S = (Q*scale) @ K^T ----
        float sacc[2][8][4];
        #pragma unroll
        for (int mi = 0; mi < 2; mi++)
            #pragma unroll
            for (int ni = 0; ni < 8; ni++)
                #pragma unroll
                for (int k = 0; k < 4; k++) sacc[mi][ni][k] = 0.f;

        #pragma unroll
        for (int j = 0; j < 8; j++) {
            uint32_t qa[2][4];
            #pragma unroll
            for (int mi = 0; mi < 2; mi++) {
                int row = wid * 32 + mi * 16 + g;
                qa[mi][0] = Qs[row * 68 + j * 8 + t];
                qa[mi][1] = Qs[(row + 8) * 68 + j * 8 + t];
                qa[mi][2] = Qs[row * 68 + j * 8 + t + 4];
                qa[mi][3] = Qs[(row + 8) * 68 + j * 8 + t + 4];
            }
            #pragma unroll
            for (int ni = 0; ni < 8; ni++) {
                uint32_t b0 = Ks[(ni * 8 + g) * 68 + j * 8 + t];
                uint32_t b1 = Ks[(ni * 8 + g) * 68 + j * 8 + t + 4];
                mma_tf32(sacc[0][ni], qa[0][0], qa[0][1], qa[0][2], qa[0][3], b0, b1);
                mma_tf32(sacc[1][ni], qa[1][0], qa[1][1], qa[1][2], qa[1][3], b0, b1);
            }
        }

        // ---- causal mask (only on the diagonal band tiles) ----
        if (jt >= 2 * bx) {
            #pragma unroll
            for (int mi = 0; mi < 2; mi++) {
                int row0 = qb + wid * 32 + mi * 16 + g;
                #pragma unroll
                for (int ni = 0; ni < 8; ni++) {
                    int col0 = jt * 64 + ni * 8 + 2 * t;
                    if (col0     > row0)     sacc[mi][ni][0] = -1e30f;
                    if (col0 + 1 > row0)     sacc[mi][ni][1] = -1e30f;
                    if (col0     > row0 + 8) sacc[mi][ni][2] = -1e30f;
                    if (col0 + 1 > row0 + 8) sacc[mi][ni][3] = -1e30f;
                }
            }
        }

        // ---- online softmax on fragments ----
        #pragma unroll
        for (int rm = 0; rm < 4; rm++) {
            const int mi = rm >> 1;
            const int c0 = (rm & 1) * 2;      // 0 -> regs 0,1 (row g); 2 -> regs 2,3 (row g+8)
            float mx = -1e30f;
            #pragma unroll
            for (int ni = 0; ni < 8; ni++)
                mx = fmaxf(mx, fmaxf(sacc[mi][ni][c0], sacc[mi][ni][c0 + 1]));
            mx = fmaxf(mx, __shfl_xor_sync(0xffffffffu, mx, 1));
            mx = fmaxf(mx, __shfl_xor_sync(0xffffffffu, mx, 2));
            float mn = fmaxf(m[rm], mx);
            float alpha = __expf(m[rm] - mn);
            float rs = 0.f;
            #pragma unroll
            for (int ni = 0; ni < 8; ni++) {
                float p0 = __expf(sacc[mi][ni][c0] - mn);
                float p1 = __expf(sacc[mi][ni][c0 + 1] - mn);
                sacc[mi][ni][c0] = p0;
                sacc[mi][ni][c0 + 1] = p1;
                rs += p0 + p1;
            }
            rs += __shfl_xor_sync(0xffffffffu, rs, 1);
            rs += __shfl_xor_sync(0xffffffffu, rs, 2);
            l[rm] = l[rm] * alpha + rs;
            m[rm] = mn;
            #pragma unroll
            for (int ni = 0; ni < 8; ni++) {
                o[mi][ni][c0] *= alpha;
                o[mi][ni][c0 + 1] *= alpha;
            }
        }

        // ---- stage P (tf32) to per-warp smem slice ----
        #pragma unroll
        for (int mi = 0; mi < 2; mi++) {
            int row = wid * 32 + mi * 16 + g;
            #pragma unroll
            for (int ni = 0; ni < 8; ni++) {
                uint2 p01, p23;
                p01.x = f2tf32(sacc[mi][ni][0]);
                p01.y = f2tf32(sacc[mi][ni][1]);
                p23.x = f2tf32(sacc[mi][ni][2]);
                p23.y = f2tf32(sacc[mi][ni][3]);
                *(uint2*)&Ps[row * 68 + ni * 8 + 2 * t] = p01;
                *(uint2*)&Ps[(row + 8) * 68 + ni * 8 + 2 * t] = p23;
            }
        }
        __syncwarp();

        // ---- O += P @ V ----
        #pragma unroll
        for (int j = 0; j < 8; j++) {
            uint32_t pa[2][4];
            #pragma unroll
            for (int mi = 0; mi < 2; mi++) {
                int row = wid * 32 + mi * 16 + g;
                pa[mi][0] = Ps[row * 68 + j * 8 + t];
                pa[mi][1] = Ps[(row + 8) * 68 + j * 8 + t];
                pa[mi][2] = Ps[row * 68 + j * 8 + t + 4];
                pa[mi][3] = Ps[(row + 8) * 68 + j * 8 + t + 4];
            }
            #pragma unroll
            for (int ni = 0; ni < 8; ni++) {
                uint32_t b0 = Vs[(j * 8 + t) * 72 + ni * 8 + g];
                uint32_t b1 = Vs[(j * 8 + t + 4) * 72 + ni * 8 + g];
                mma_tf32(o[0][ni], pa[0][0], pa[0][1], pa[0][2], pa[0][3], b0, b1);
                mma_tf32(o[1][ni], pa[1][0], pa[1][1], pa[1][2], pa[1][3], b0, b1);
            }
        }
    }

    // ---- epilogue: y = O / l ----
    float* yb = y + (size_t)b * TSEQ * C_EMBD + h * HD;
    #pragma unroll
    for (int mi = 0; mi < 2; mi++) {
        #pragma unroll
        for (int hf = 0; hf < 2; hf++) {
            const int rm = mi * 2 + hf;
            const float inv = 1.f / l[rm];
            const int row = qb + wid * 32 + mi * 16 + hf * 8 + g;
            #pragma unroll
            for (int ni = 0; ni < 8; ni++) {
                float2 v;
                v.x = o[mi][ni][hf * 2] * inv;
                v.y = o[mi][ni][hf * 2 + 1] * inv;
                *(float2*)&yb[(size_t)row * C_EMBD + ni * 8 + 2 * t] = v;
            }
        }
    }
}

// ---------------------------------------------------------------------------
extern "C" void kernel_launch(void* const* d_in, const int* in_sizes, int n_in,
                              void* d_out, int out_size)
{
    const float* x      = (const float*)d_in[0];
    const float* W_attn = (const float*)d_in[1];
    const float* b_attn = (const float*)d_in[2];
    const float* W_proj = (const float*)d_in[3];
    const float* b_proj = (const float*)d_in[4];
    float* out = (float*)d_out;

    float *qkv, *y, *WaT, *WpT;
    cudaGetSymbolAddress((void**)&qkv, g_qkv);
    cudaGetSymbolAddress((void**)&y, g_y);
    cudaGetSymbolAddress((void**)&WaT, g_WaT);
    cudaGetSymbolAddress((void**)&WpT, g_WpT);

    const int M = BATCH * TSEQ;  // 8192

    static int attr_set = 0;
    if (!attr_set) {
        cudaFuncSetAttribute(tf32_gemm_kernel,
                             cudaFuncAttributeMaxDynamicSharedMemorySize, GEMM_SMEM);
        cudaFuncSetAttribute(attn_tc_kernel,
                             cudaFuncAttributeMaxDynamicSharedMemorySize, ATT_SMEM);
        attr_set = 1;
    }

    // 0) Pre-transpose weights
    {
        dim3 g1(3 * C_EMBD / 32, C_EMBD / 32);
        transpose_kernel<<<g1, 256>>>(W_attn, WaT, C_EMBD, 3 * C_EMBD);
        dim3 g2(C_EMBD / 32, C_EMBD / 32);
        transpose_kernel<<<g2, 256>>>(W_proj, WpT, C_EMBD, C_EMBD);
    }

    // 1) QKV GEMM
    {
        dim3 grid(3 * C_EMBD / 128, M / 128);
        tf32_gemm_kernel<<<grid, 256, GEMM_SMEM>>>(x, WaT, b_attn, qkv,
                                                   M, 3 * C_EMBD, C_EMBD);
    }

    // 2) Tensor-core flash attention
    {
        dim3 grid(TSEQ / 128, NH, BATCH);
        attn_tc_kernel<<<grid, 128, ATT_SMEM>>>(qkv, y);
    }

    // 3) Output projection
    {
        dim3 grid(C_EMBD / 128, M / 128);
        tf32_gemm_kernel<<<grid, 256, GEMM_SMEM>>>(y, WpT, b_proj, out,
                                                   M, C_EMBD, C_EMBD);
    }
}

// round 5
// speedup vs baseline: 3.9549x; 1.0779x over previous
#include <cuda_runtime.h>
#include <cstdint>
#include <math.h>

#define C_EMBD 1024
#define NH     16
#define HD     64
#define TSEQ   2048
#define BATCH  4

__device__ float g_qkv[(size_t)BATCH * TSEQ * 3 * C_EMBD];  // tf32 bits (q pre-scaled)
__device__ float g_y[(size_t)BATCH * TSEQ * C_EMBD];        // tf32 bits
__device__ float g_xc[(size_t)BATCH * TSEQ * C_EMBD];       // x, tf32 bits
__device__ float g_WaT[(size_t)3 * C_EMBD * C_EMBD];        // tf32 bits
__device__ float g_WpT[(size_t)C_EMBD * C_EMBD];            // tf32 bits

// ---------------------------------------------------------------------------
// Helpers
// ---------------------------------------------------------------------------
__device__ __forceinline__ uint32_t smem_u32(const void* p) {
    uint32_t a;
    asm("{ .reg .u64 t; cvta.to.shared.u64 t, %1; cvt.u32.u64 %0, t; }" : "=r"(a) : "l"(p));
    return a;
}
__device__ __forceinline__ void cp_async16(uint32_t dst, const void* src) {
    asm volatile("cp.async.cg.shared.global [%0], [%1], 16;" :: "r"(dst), "l"(src) : "memory");
}
__device__ __forceinline__ void cp_commit() {
    asm volatile("cp.async.commit_group;" ::: "memory");
}
template <int N>
__device__ __forceinline__ void cp_wait() {
    asm volatile("cp.async.wait_group %0;" :: "n"(N) : "memory");
}
__device__ __forceinline__ uint32_t f2tf32(float x) {
    uint32_t y;
    asm("cvt.rna.tf32.f32 %0, %1;" : "=r"(y) : "f"(x));
    return y;
}
__device__ __forceinline__ void mma_tf32(float* c, uint32_t a0, uint32_t a1,
                                         uint32_t a2, uint32_t a3,
                                         uint32_t b0, uint32_t b1) {
    asm volatile(
        "mma.sync.aligned.m16n8k8.row.col.f32.tf32.tf32.f32 "
        "{%0,%1,%2,%3}, {%4,%5,%6,%7}, {%8,%9}, {%0,%1,%2,%3};"
        : "+f"(c[0]), "+f"(c[1]), "+f"(c[2]), "+f"(c[3])
        : "r"(a0), "r"(a1), "r"(a2), "r"(a3), "r"(b0), "r"(b1));
}
__device__ __forceinline__ int tile_idx(int row, int k) {
    return row * 32 + ((((k >> 2) + row) & 7) << 2) + (k & 3);
}

// ---------------------------------------------------------------------------
// Elementwise tf32 convert (for x)
// ---------------------------------------------------------------------------
__global__ __launch_bounds__(256)
void cvt_tf32_kernel(const float4* __restrict__ in, uint4* __restrict__ out)
{
    int i = blockIdx.x * 256 + threadIdx.x;
    float4 v = in[i];
    uint4 u;
    u.x = f2tf32(v.x); u.y = f2tf32(v.y); u.z = f2tf32(v.z); u.w = f2tf32(v.w);
    out[i] = u;
}

// ---------------------------------------------------------------------------
// Weight transpose + tf32 convert: W[R][Ncols] -> WT[Ncols][R] (tf32 bits)
// ---------------------------------------------------------------------------
__global__ __launch_bounds__(256)
void transpose_kernel(const float* __restrict__ W, float* __restrict__ WT,
                      int R, int Ncols)
{
    __shared__ float t[32][33];
    const int bx = blockIdx.x * 32;
    const int by = blockIdx.y * 32;
    const int tx = threadIdx.x & 31;
    const int ty8 = threadIdx.x >> 5;
    #pragma unroll
    for (int i = 0; i < 32; i += 8)
        t[ty8 + i][tx] = W[(size_t)(by + ty8 + i) * Ncols + bx + tx];
    __syncthreads();
    #pragma unroll
    for (int i = 0; i < 32; i += 8)
        WT[(size_t)(bx + ty8 + i) * R + by + tx] =
            __uint_as_float(f2tf32(t[tx][ty8 + i]));
}

// ---------------------------------------------------------------------------
// tf32 mma.sync GEMM with bias: C[M,N] = A[M,K] @ BT[N,K]^T + bias[N]
// A/BT hold pre-converted tf32 bit patterns. 3-stage cp.async pipeline.
// mode 0: plain f32 store. mode 1 (qkv): scale cols<C_EMBD by 0.125, tf32 store.
// ---------------------------------------------------------------------------
#define GEMM_SMEM 98304

__global__ __launch_bounds__(256, 1)
void tf32_gemm_kernel(const float* __restrict__ A,
                      const float* __restrict__ BT,
                      const float* __restrict__ bias,
                      float* __restrict__ Cm,
                      int M, int N, int K, int mode)
{
    extern __shared__ char smem[];
    const uint32_t sb = smem_u32(smem);
    uint32_t* const Su = (uint32_t*)smem;

    const int tid = threadIdx.x;
    const int wid = tid >> 5;
    const int lane = tid & 31;
    const int g = lane >> 2;
    const int t = lane & 3;
    const int wm = wid >> 2;
    const int wn = wid & 3;

    const int bm0 = blockIdx.y * 128;
    const int bn0 = blockIdx.x * 128;
    const int NS = K >> 5;

    float acc[4][4][4];
    #pragma unroll
    for (int i = 0; i < 4; i++)
        #pragma unroll
        for (int j = 0; j < 4; j++)
            #pragma unroll
            for (int r = 0; r < 4; r++) acc[i][j][r] = 0.f;

    auto load_stage = [&](int s) {
        const int k0 = s * 32;
        const int buf = s % 3;
        const uint32_t sA = sb + buf * 16384;
        const uint32_t sB = sb + 49152 + buf * 16384;
        #pragma unroll
        for (int it = 0; it < 4; it++) {
            int idx = it * 256 + tid;
            int r = idx >> 3, ck = idx & 7;
            uint32_t d = sA + r * 128 + ((((ck + r) & 7)) << 4);
            cp_async16(d, &A[(size_t)(bm0 + r) * K + k0 + ck * 4]);
        }
        #pragma unroll
        for (int it = 0; it < 4; it++) {
            int idx = it * 256 + tid;
            int r = idx >> 3, ck = idx & 7;
            uint32_t d = sB + r * 128 + ((((ck + r) & 7)) << 4);
            cp_async16(d, &BT[(size_t)(bn0 + r) * K + k0 + ck * 4]);
        }
        cp_commit();
    };

    load_stage(0);
    load_stage(1);

    for (int s = 0; s < NS; s++) {
        if (s + 2 < NS) { load_stage(s + 2); cp_wait<2>(); }
        else if (s + 1 < NS) { cp_wait<1>(); }
        else { cp_wait<0>(); }
        __syncthreads();

        const int buf = s % 3;
        const uint32_t* As = Su + buf * 4096;
        const uint32_t* Bs = Su + 12288 + buf * 4096;

        #pragma unroll
        for (int ks = 0; ks < 4; ks++) {
            const int kb = ks * 8;
            uint32_t afr[4][4];
            #pragma unroll
            for (int mi = 0; mi < 4; mi++) {
                int m = wm * 64 + mi * 16 + g;
                afr[mi][0] = As[tile_idx(m,     kb + t)];
                afr[mi][1] = As[tile_idx(m + 8, kb + t)];
                afr[mi][2] = As[tile_idx(m,     kb + t + 4)];
                afr[mi][3] = As[tile_idx(m + 8, kb + t + 4)];
            }
            uint32_t bfr[4][2];
            #pragma unroll
            for (int ni = 0; ni < 4; ni++) {
                int n = wn * 32 + ni * 8 + g;
                bfr[ni][0] = Bs[tile_idx(n, kb + t)];
                bfr[ni][1] = Bs[tile_idx(n, kb + t + 4)];
            }
            #pragma unroll
            for (int mi = 0; mi < 4; mi++)
                #pragma unroll
                for (int ni = 0; ni < 4; ni++)
                    mma_tf32(acc[mi][ni],
                             afr[mi][0], afr[mi][1], afr[mi][2], afr[mi][3],
                             bfr[ni][0], bfr[ni][1]);
        }
        __syncthreads();
    }

    #pragma unroll
    for (int mi = 0; mi < 4; mi++) {
        #pragma unroll
        for (int ni = 0; ni < 4; ni++) {
            int row0 = bm0 + wm * 64 + mi * 16 + g;
            int col  = bn0 + wn * 32 + ni * 8 + 2 * t;
            float bx = bias[col], by = bias[col + 1];
            float v00 = acc[mi][ni][0] + bx, v01 = acc[mi][ni][1] + by;
            float v10 = acc[mi][ni][2] + bx, v11 = acc[mi][ni][3] + by;
            if (mode == 1) {
                if (col < C_EMBD) {  // q region: fold in softmax scale
                    v00 *= 0.125f; v01 *= 0.125f; v10 *= 0.125f; v11 *= 0.125f;
                }
                v00 = __uint_as_float(f2tf32(v00));
                v01 = __uint_as_float(f2tf32(v01));
                v10 = __uint_as_float(f2tf32(v10));
                v11 = __uint_as_float(f2tf32(v11));
            }
            float2 w0 = {v00, v01}, w1 = {v10, v11};
            *(float2*)&Cm[(size_t)row0 * N + col] = w0;
            *(float2*)&Cm[(size_t)(row0 + 8) * N + col] = w1;
        }
    }
}

// ---------------------------------------------------------------------------
// Tensor-core flash attention (tf32), causal. qkv pre-converted to tf32 bits
// (q pre-scaled). cp.async double-buffered K/V; P via register transpose.
// smem (u32): Qs[128][68] @0, Ks[2][64][68] @8704, Vs[2][64][72] @17408.
// Total 106496 bytes -> 2 CTA/SM.
// ---------------------------------------------------------------------------
#define ATT_SMEM 106496

__global__ __launch_bounds__(128, 1)
void attn_tc_kernel(const float* __restrict__ qkv, float* __restrict__ y)
{
    extern __shared__ uint32_t smu[];
    const uint32_t sb = smem_u32(smu);

    const int tid = threadIdx.x;
    const int wid = tid >> 5;
    const int lane = tid & 31;
    const int g = lane >> 2;
    const int t = lane & 3;
    const int bx = (gridDim.x - 1) - blockIdx.x;   // heavy tiles first
    const int h = blockIdx.y;
    const int b = blockIdx.z;
    const int qb = bx * 128;

    const float* base = qkv + (size_t)b * TSEQ * (3 * C_EMBD) + h * HD;

    auto issue_kv = [&](int jt) {
        const uint32_t sk = sb + (8704 + (jt & 1) * 4352) * 4;
        const uint32_t sv = sb + (17408 + (jt & 1) * 4608) * 4;
        #pragma unroll
        for (int it = 0; it < 8; it++) {
            int idx = it * 128 + tid;
            int r = idx >> 4, c4 = idx & 15;
            const float* rp = &base[(size_t)(jt * 64 + r) * (3 * C_EMBD) + c4 * 4];
            cp_async16(sk + (r * 68 + c4 * 4) * 4, rp + C_EMBD);
            cp_async16(sv + (r * 72 + c4 * 4) * 4, rp + 2 * C_EMBD);
        }
    };

    // Prologue: Q tile + KV tile 0 in one group.
    #pragma unroll
    for (int it = 0; it < 16; it++) {
        int idx = it * 128 + tid;
        int r = idx >> 4, c4 = idx & 15;
        cp_async16(sb + (r * 68 + c4 * 4) * 4,
                   &base[(size_t)(qb + r) * (3 * C_EMBD) + c4 * 4]);
    }
    issue_kv(0);
    cp_commit();

    float m[4], l[4], o[2][8][4];
    #pragma unroll
    for (int rm = 0; rm < 4; rm++) { m[rm] = -1e30f; l[rm] = 0.f; }
    #pragma unroll
    for (int mi = 0; mi < 2; mi++)
        #pragma unroll
        for (int ni = 0; ni < 8; ni++)
            #pragma unroll
            for (int k = 0; k < 4; k++) o[mi][ni][k] = 0.f;

    const uint32_t* const Qs = smu;
    const int ntiles = 2 * bx + 2;

    for (int jt = 0; jt < ntiles; jt++) {
        if (jt + 1 < ntiles) { issue_kv(jt + 1); cp_commit(); cp_wait<1>(); }
        else { cp_wait<0>(); }
        __syncthreads();

        const uint32_t* K = smu + 8704 + (jt & 1) * 4352;
        const uint32_t* V = smu + 17408 + (jt & 1) * 4608;

        // ---- S = Q @ K^T (Q pre-scaled) ----
        float sacc[2][8][4];
        #pragma unroll
        for (int mi = 0; mi < 2; mi++)
            #pragma unroll
            for (int ni = 0; ni < 8; ni++)
                #pragma unroll
                for (int k = 0; k < 4; k++) sacc[mi][ni][k] = 0.f;

        #pragma unroll
        for (int j = 0; j < 8; j++) {
            uint32_t qa[2][4];
            #pragma unroll
            for (int mi = 0; mi < 2; mi++) {
                int row = wid * 32 + mi * 16 + g;
                qa[mi][0] = Qs[row * 68 + j * 8 + t];
                qa[mi][1] = Qs[(row + 8) * 68 + j * 8 + t];
                qa[mi][2] = Qs[row * 68 + j * 8 + t + 4];
                qa[mi][3] = Qs[(row + 8) * 68 + j * 8 + t + 4];
            }
            #pragma unroll
            for (int ni = 0; ni < 8; ni++) {
                uint32_t b0 = K[(ni * 8 + g) * 68 + j * 8 + t];
                uint32_t b1 = K[(ni * 8 + g) * 68 + j * 8 + t + 4];
                mma_tf32(sacc[0][ni], qa[0][0], qa[0][1], qa[0][2], qa[0][3], b0, b1);
                mma_tf32(sacc[1][ni], qa[1][0], qa[1][1], qa[1][2], qa[1][3], b0, b1);
            }
        }

        // ---- causal mask on diagonal band ----
        if (jt >= 2 * bx) {
            #pragma unroll
            for (int mi = 0; mi < 2; mi++) {
                int row0 = qb + wid * 32 + mi * 16 + g;
                #pragma unroll
                for (int ni = 0; ni < 8; ni++) {
                    int col0 = jt * 64 + ni * 8 + 2 * t;
                    if (col0     > row0)     sacc[mi][ni][0] = -1e30f;
                    if (col0 + 1 > row0)     sacc[mi][ni][1] = -1e30f;
                    if (col0     > row0 + 8) sacc[mi][ni][2] = -1e30f;
                    if (col0 + 1 > row0 + 8) sacc[mi][ni][3] = -1e30f;
                }
            }
        }

        // ---- online softmax ----
        #pragma unroll
        for (int rm = 0; rm < 4; rm++) {
            const int mi = rm >> 1;
            const int c0 = (rm & 1) * 2;
            float mx = -1e30f;
            #pragma unroll
            for (int ni = 0; ni < 8; ni++)
                mx = fmaxf(mx, fmaxf(sacc[mi][ni][c0], sacc[mi][ni][c0 + 1]));
            mx = fmaxf(mx, __shfl_xor_sync(0xffffffffu, mx, 1));
            mx = fmaxf(mx, __shfl_xor_sync(0xffffffffu, mx, 2));
            float mn = fmaxf(m[rm], mx);
            float alpha = __expf(m[rm] - mn);
            float rs = 0.f;
            #pragma unroll
            for (int ni = 0; ni < 8; ni++) {
                float p0 = __expf(sacc[mi][ni][c0] - mn);
                float p1 = __expf(sacc[mi][ni][c0 + 1] - mn);
                sacc[mi][ni][c0] = p0;
                sacc[mi][ni][c0 + 1] = p1;
                rs += p0 + p1;
            }
            rs += __shfl_xor_sync(0xffffffffu, rs, 1);
            rs += __shfl_xor_sync(0xffffffffu, rs, 2);
            l[rm] = l[rm] * alpha + rs;
            m[rm] = mn;
            #pragma unroll
            for (int ni = 0; ni < 8; ni++) {
                o[mi][ni][c0] *= alpha;
                o[mi][ni][c0 + 1] *= alpha;
            }
        }

        // ---- O += P @ V via register C-frag -> A-frag transpose ----
        const int s0 = (lane & 28) | (t >> 1);
        const int s1 = s0 + 2;
        const bool odd = (t & 1);
        #pragma unroll
        for (int j = 0; j < 8; j++) {
            uint32_t pa[2][4];
            #pragma unroll
            for (int mi = 0; mi < 2; mi++) {
                float c0v = sacc[mi][j][0], c1v = sacc[mi][j][1];
                float c2v = sacc[mi][j][2], c3v = sacc[mi][j][3];
                float q00 = __shfl_sync(0xffffffffu, c0v, s0);
                float q01 = __shfl_sync(0xffffffffu, c1v, s0);
                float q10 = __shfl_sync(0xffffffffu, c2v, s0);
                float q11 = __shfl_sync(0xffffffffu, c3v, s0);
                float r00 = __shfl_sync(0xffffffffu, c0v, s1);
                float r01 = __shfl_sync(0xffffffffu, c1v, s1);
                float r10 = __shfl_sync(0xffffffffu, c2v, s1);
                float r11 = __shfl_sync(0xffffffffu, c3v, s1);
                pa[mi][0] = f2tf32(odd ? q01 : q00);
                pa[mi][1] = f2tf32(odd ? q11 : q10);
                pa[mi][2] = f2tf32(odd ? r01 : r00);
                pa[mi][3] = f2tf32(odd ? r11 : r10);
            }
            #pragma unroll
            for (int ni = 0; ni < 8; ni++) {
                uint32_t b0 = V[(j * 8 + t) * 72 + ni * 8 + g];
                uint32_t b1 = V[(j * 8 + t + 4) * 72 + ni * 8 + g];
                mma_tf32(o[0][ni], pa[0][0], pa[0][1], pa[0][2], pa[0][3], b0, b1);
                mma_tf32(o[1][ni], pa[1][0], pa[1][1], pa[1][2], pa[1][3], b0, b1);
            }
        }
        __syncthreads();  // all warps done with this KV buffer
    }

    // ---- epilogue: y = O / l, tf32 bits (consumed by GEMM2) ----
    float* yb = y + (size_t)b * TSEQ * C_EMBD + h * HD;
    #pragma unroll
    for (int mi = 0; mi < 2; mi++) {
        #pragma unroll
        for (int hf = 0; hf < 2; hf++) {
            const int rm = mi * 2 + hf;
            const float inv = 1.f / l[rm];
            const int row = qb + wid * 32 + mi * 16 + hf * 8 + g;
            #pragma unroll
            for (int ni = 0; ni < 8; ni++) {
                float2 v;
                v.x = __uint_as_float(f2tf32(o[mi][ni][hf * 2] * inv));
                v.y = __uint_as_float(f2tf32(o[mi][ni][hf * 2 + 1] * inv));
                *(float2*)&yb[(size_t)row * C_EMBD + ni * 8 + 2 * t] = v;
            }
        }
    }
}

// ---------------------------------------------------------------------------
extern "C" void kernel_launch(void* const* d_in, const int* in_sizes, int n_in,
                              void* d_out, int out_size)
{
    const float* x      = (const float*)d_in[0];
    const float* W_attn = (const float*)d_in[1];
    const float* b_attn = (const float*)d_in[2];
    const float* W_proj = (const float*)d_in[3];
    const float* b_proj = (const float*)d_in[4];
    float* out = (float*)d_out;

    float *qkv, *y, *xc, *WaT, *WpT;
    cudaGetSymbolAddress((void**)&qkv, g_qkv);
    cudaGetSymbolAddress((void**)&y, g_y);
    cudaGetSymbolAddress((void**)&xc, g_xc);
    cudaGetSymbolAddress((void**)&WaT, g_WaT);
    cudaGetSymbolAddress((void**)&WpT, g_WpT);

    const int M = BATCH * TSEQ;  // 8192

    static int attr_set = 0;
    if (!attr_set) {
        cudaFuncSetAttribute(tf32_gemm_kernel,
                             cudaFuncAttributeMaxDynamicSharedMemorySize, GEMM_SMEM);
        cudaFuncSetAttribute(attn_tc_kernel,
                             cudaFuncAttributeMaxDynamicSharedMemorySize, ATT_SMEM);
        attr_set = 1;
    }

    // 0) Producers: convert x; transpose+convert weights
    {
        cvt_tf32_kernel<<<(M * C_EMBD) / 1024, 256>>>((const float4*)x, (uint4*)xc);
        dim3 g1(3 * C_EMBD / 32, C_EMBD / 32);
        transpose_kernel<<<g1, 256>>>(W_attn, WaT, C_EMBD, 3 * C_EMBD);
        dim3 g2(C_EMBD / 32, C_EMBD / 32);
        transpose_kernel<<<g2, 256>>>(W_proj, WpT, C_EMBD, C_EMBD);
    }

    // 1) QKV GEMM (epilogue: scale q, convert to tf32)
    {
        dim3 grid(3 * C_EMBD / 128, M / 128);
        tf32_gemm_kernel<<<grid, 256, GEMM_SMEM>>>(xc, WaT, b_attn, qkv,
                                                   M, 3 * C_EMBD, C_EMBD, 1);
    }

    // 2) Tensor-core flash attention
    {
        dim3 grid(TSEQ / 128, NH, BATCH);
        attn_tc_kernel<<<grid, 128, ATT_SMEM>>>(qkv, y);
    }

    // 3) Output projection (plain f32 epilogue)
    {
        dim3 grid(C_EMBD / 128, M / 128);
        tf32_gemm_kernel<<<grid, 256, GEMM_SMEM>>>(y, WpT, b_proj, out,
                                                   M, C_EMBD, C_EMBD, 0);
    }
}

// round 6
// speedup vs baseline: 4.3772x; 1.1068x over previous
#include <cuda_runtime.h>
#include <cstdint>
#include <math.h>

#define C_EMBD 1024
#define NH     16
#define HD     64
#define TSEQ   2048
#define BATCH  4

__device__ float g_qkv[(size_t)BATCH * TSEQ * 3 * C_EMBD];  // tf32 bits (q pre-scaled)
__device__ float g_y[(size_t)BATCH * TSEQ * C_EMBD];        // tf32 bits
__device__ float g_xc[(size_t)BATCH * TSEQ * C_EMBD];       // x, tf32 bits
__device__ float g_WaT[(size_t)3 * C_EMBD * C_EMBD];        // tf32 bits
__device__ float g_WpT[(size_t)C_EMBD * C_EMBD];            // tf32 bits

// ---------------------------------------------------------------------------
// Helpers
// ---------------------------------------------------------------------------
__device__ __forceinline__ uint32_t smem_u32(const void* p) {
    uint32_t a;
    asm("{ .reg .u64 t; cvta.to.shared.u64 t, %1; cvt.u32.u64 %0, t; }" : "=r"(a) : "l"(p));
    return a;
}
__device__ __forceinline__ void cp_async16(uint32_t dst, const void* src) {
    asm volatile("cp.async.cg.shared.global [%0], [%1], 16;" :: "r"(dst), "l"(src) : "memory");
}
__device__ __forceinline__ void cp_commit() {
    asm volatile("cp.async.commit_group;" ::: "memory");
}
template <int N>
__device__ __forceinline__ void cp_wait() {
    asm volatile("cp.async.wait_group %0;" :: "n"(N) : "memory");
}
__device__ __forceinline__ uint32_t f2tf32(float x) {
    uint32_t y;
    asm("cvt.rna.tf32.f32 %0, %1;" : "=r"(y) : "f"(x));
    return y;
}
__device__ __forceinline__ void mma_tf32(float* c, uint32_t a0, uint32_t a1,
                                         uint32_t a2, uint32_t a3,
                                         uint32_t b0, uint32_t b1) {
    asm volatile(
        "mma.sync.aligned.m16n8k8.row.col.f32.tf32.tf32.f32 "
        "{%0,%1,%2,%3}, {%4,%5,%6,%7}, {%8,%9}, {%0,%1,%2,%3};"
        : "+f"(c[0]), "+f"(c[1]), "+f"(c[2]), "+f"(c[3])
        : "r"(a0), "r"(a1), "r"(a2), "r"(a3), "r"(b0), "r"(b1));
}
__device__ __forceinline__ void ldsm_x4(uint32_t& r0, uint32_t& r1,
                                        uint32_t& r2, uint32_t& r3, uint32_t addr) {
    asm volatile("ldmatrix.sync.aligned.m8n8.x4.shared.b16 {%0,%1,%2,%3}, [%4];"
                 : "=r"(r0), "=r"(r1), "=r"(r2), "=r"(r3) : "r"(addr));
}

// ---------------------------------------------------------------------------
// Elementwise tf32 convert (for x)
// ---------------------------------------------------------------------------
__global__ __launch_bounds__(256)
void cvt_tf32_kernel(const float4* __restrict__ in, uint4* __restrict__ out)
{
    int i = blockIdx.x * 256 + threadIdx.x;
    float4 v = in[i];
    uint4 u;
    u.x = f2tf32(v.x); u.y = f2tf32(v.y); u.z = f2tf32(v.z); u.w = f2tf32(v.w);
    out[i] = u;
}

// ---------------------------------------------------------------------------
// Weight transpose + tf32 convert: W[R][Ncols] -> WT[Ncols][R] (tf32 bits)
// ---------------------------------------------------------------------------
__global__ __launch_bounds__(256)
void transpose_kernel(const float* __restrict__ W, float* __restrict__ WT,
                      int R, int Ncols)
{
    __shared__ float t[32][33];
    const int bx = blockIdx.x * 32;
    const int by = blockIdx.y * 32;
    const int tx = threadIdx.x & 31;
    const int ty8 = threadIdx.x >> 5;
    #pragma unroll
    for (int i = 0; i < 32; i += 8)
        t[ty8 + i][tx] = W[(size_t)(by + ty8 + i) * Ncols + bx + tx];
    __syncthreads();
    #pragma unroll
    for (int i = 0; i < 32; i += 8)
        WT[(size_t)(bx + ty8 + i) * R + by + tx] =
            __uint_as_float(f2tf32(t[tx][ty8 + i]));
}

// ---------------------------------------------------------------------------
// tf32 mma.sync GEMM with bias. Pre-converted tf32 inputs.
// 4 smem buffers, prefetch distance 2, ONE barrier/stage, ldmatrix fragments.
// ---------------------------------------------------------------------------
#define GEMM_SMEM 131072

__global__ __launch_bounds__(256, 1)
void tf32_gemm_kernel(const float* __restrict__ A,
                      const float* __restrict__ BT,
                      const float* __restrict__ bias,
                      float* __restrict__ Cm,
                      int M, int N, int K, int mode)
{
    extern __shared__ char smem[];
    const uint32_t sb = smem_u32(smem);

    const int tid = threadIdx.x;
    const int wid = tid >> 5;
    const int lane = tid & 31;
    const int g = lane >> 2;
    const int t = lane & 3;
    const int wm = wid >> 2;
    const int wn = wid & 3;

    const int bm0 = blockIdx.y * 128;
    const int bn0 = blockIdx.x * 128;
    const int NS = K >> 5;

    // ldmatrix per-lane geometry
    const int a_lrow = (lane & 7) | ((lane & 8)  ? 8 : 0);
    const int a_sel  = lane >> 4;                 // +0/+1 chunk
    const int b_lrow = (lane & 7) | ((lane & 16) ? 8 : 0);
    const int b_sel  = (lane >> 3) & 1;
    uint32_t a_off[4], a_rot[4], b_off[2], b_rot[2];
    #pragma unroll
    for (int mi = 0; mi < 4; mi++) {
        int row = wm * 64 + mi * 16 + a_lrow;
        a_off[mi] = (uint32_t)row << 7;           // row * 128 bytes
        a_rot[mi] = row & 7;
    }
    #pragma unroll
    for (int nip = 0; nip < 2; nip++) {
        int row = wn * 32 + nip * 16 + b_lrow;
        b_off[nip] = (uint32_t)row << 7;
        b_rot[nip] = row & 7;
    }

    float acc[4][4][4];
    #pragma unroll
    for (int i = 0; i < 4; i++)
        #pragma unroll
        for (int j = 0; j < 4; j++)
            #pragma unroll
            for (int r = 0; r < 4; r++) acc[i][j][r] = 0.f;

    auto load_stage = [&](int s) {
        const int k0 = s * 32;
        const int buf = s & 3;
        const uint32_t sA = sb + buf * 16384;
        const uint32_t sB = sb + 65536 + buf * 16384;
        #pragma unroll
        for (int it = 0; it < 4; it++) {
            int idx = it * 256 + tid;
            int r = idx >> 3, ck = idx & 7;
            uint32_t d = sA + r * 128 + ((((ck + r) & 7)) << 4);
            cp_async16(d, &A[(size_t)(bm0 + r) * K + k0 + ck * 4]);
        }
        #pragma unroll
        for (int it = 0; it < 4; it++) {
            int idx = it * 256 + tid;
            int r = idx >> 3, ck = idx & 7;
            uint32_t d = sB + r * 128 + ((((ck + r) & 7)) << 4);
            cp_async16(d, &BT[(size_t)(bn0 + r) * K + k0 + ck * 4]);
        }
        cp_commit();
    };

    load_stage(0);
    load_stage(1);

    for (int s = 0; s < NS; s++) {
        if (s + 2 < NS) { load_stage(s + 2); cp_wait<2>(); }
        else if (s + 1 < NS) { cp_wait<1>(); }
        else { cp_wait<0>(); }
        __syncthreads();

        const int buf = s & 3;
        const uint32_t sA = sb + buf * 16384;
        const uint32_t sB = sb + 65536 + buf * 16384;

        #pragma unroll
        for (int ks = 0; ks < 4; ks++) {
            const int ckA = 2 * ks + a_sel;
            const int ckB = 2 * ks + b_sel;
            uint32_t afr[4][4];
            #pragma unroll
            for (int mi = 0; mi < 4; mi++)
                ldsm_x4(afr[mi][0], afr[mi][1], afr[mi][2], afr[mi][3],
                        sA + a_off[mi] + (((ckA + a_rot[mi]) & 7) << 4));
            uint32_t bfr[4][2];
            #pragma unroll
            for (int nip = 0; nip < 2; nip++)
                ldsm_x4(bfr[2 * nip][0], bfr[2 * nip][1],
                        bfr[2 * nip + 1][0], bfr[2 * nip + 1][1],
                        sB + b_off[nip] + (((ckB + b_rot[nip]) & 7) << 4));
            #pragma unroll
            for (int mi = 0; mi < 4; mi++)
                #pragma unroll
                for (int ni = 0; ni < 4; ni++)
                    mma_tf32(acc[mi][ni],
                             afr[mi][0], afr[mi][1], afr[mi][2], afr[mi][3],
                             bfr[ni][0], bfr[ni][1]);
        }
    }

    #pragma unroll
    for (int mi = 0; mi < 4; mi++) {
        #pragma unroll
        for (int ni = 0; ni < 4; ni++) {
            int row0 = bm0 + wm * 64 + mi * 16 + g;
            int col  = bn0 + wn * 32 + ni * 8 + 2 * t;
            float bx = bias[col], by = bias[col + 1];
            float v00 = acc[mi][ni][0] + bx, v01 = acc[mi][ni][1] + by;
            float v10 = acc[mi][ni][2] + bx, v11 = acc[mi][ni][3] + by;
            if (mode == 1) {
                if (col < C_EMBD) {
                    v00 *= 0.125f; v01 *= 0.125f; v10 *= 0.125f; v11 *= 0.125f;
                }
                v00 = __uint_as_float(f2tf32(v00));
                v01 = __uint_as_float(f2tf32(v01));
                v10 = __uint_as_float(f2tf32(v10));
                v11 = __uint_as_float(f2tf32(v11));
            }
            float2 w0 = {v00, v01}, w1 = {v10, v11};
            *(float2*)&Cm[(size_t)row0 * N + col] = w0;
            *(float2*)&Cm[(size_t)(row0 + 8) * N + col] = w1;
        }
    }
}

// ---------------------------------------------------------------------------
// Tensor-core flash attention (tf32), causal. ldmatrix Q/K fragments,
// cp.async double-buffered K/V, register-transposed P.
// smem (u32): Qs[128][68] @0, Ks[2][64][68] @8704, Vs[2][64][72] @17408.
// ---------------------------------------------------------------------------
#define ATT_SMEM 106496

__global__ __launch_bounds__(128, 1)
void attn_tc_kernel(const float* __restrict__ qkv, float* __restrict__ y)
{
    extern __shared__ uint32_t smu[];
    const uint32_t sb = smem_u32(smu);

    const int tid = threadIdx.x;
    const int wid = tid >> 5;
    const int lane = tid & 31;
    const int g = lane >> 2;
    const int t = lane & 3;
    const int bx = (gridDim.x - 1) - blockIdx.x;   // heavy tiles first
    const int h = blockIdx.y;
    const int b = blockIdx.z;
    const int qb = bx * 128;

    const float* base = qkv + (size_t)b * TSEQ * (3 * C_EMBD) + h * HD;

    // ldmatrix per-lane geometry (stride 68 words = 272 B, no rotation)
    const int a_lrow = (lane & 7) | ((lane & 8)  ? 8 : 0);
    const int a_sel  = lane >> 4;
    const int b_lrow = (lane & 7) | ((lane & 16) ? 8 : 0);
    const int b_sel  = (lane >> 3) & 1;
    uint32_t q_addr[2];
    #pragma unroll
    for (int mi = 0; mi < 2; mi++) {
        int row = wid * 32 + mi * 16 + a_lrow;
        q_addr[mi] = sb + row * 272 + a_sel * 16;
    }
    uint32_t k_base[4];
    #pragma unroll
    for (int nip = 0; nip < 4; nip++) {
        int row = nip * 16 + b_lrow;
        k_base[nip] = row * 272 + b_sel * 16;
    }

    auto issue_kv = [&](int jt) {
        const uint32_t sk = sb + (8704 + (jt & 1) * 4352) * 4;
        const uint32_t sv = sb + (17408 + (jt & 1) * 4608) * 4;
        #pragma unroll
        for (int it = 0; it < 8; it++) {
            int idx = it * 128 + tid;
            int r = idx >> 4, c4 = idx & 15;
            const float* rp = &base[(size_t)(jt * 64 + r) * (3 * C_EMBD) + c4 * 4];
            cp_async16(sk + (r * 68 + c4 * 4) * 4, rp + C_EMBD);
            cp_async16(sv + (r * 72 + c4 * 4) * 4, rp + 2 * C_EMBD);
        }
    };

    // Prologue: Q tile + KV tile 0 in one group.
    #pragma unroll
    for (int it = 0; it < 16; it++) {
        int idx = it * 128 + tid;
        int r = idx >> 4, c4 = idx & 15;
        cp_async16(sb + (r * 68 + c4 * 4) * 4,
                   &base[(size_t)(qb + r) * (3 * C_EMBD) + c4 * 4]);
    }
    issue_kv(0);
    cp_commit();

    float m[4], l[4], o[2][8][4];
    #pragma unroll
    for (int rm = 0; rm < 4; rm++) { m[rm] = -1e30f; l[rm] = 0.f; }
    #pragma unroll
    for (int mi = 0; mi < 2; mi++)
        #pragma unroll
        for (int ni = 0; ni < 8; ni++)
            #pragma unroll
            for (int k = 0; k < 4; k++) o[mi][ni][k] = 0.f;

    const int ntiles = 2 * bx + 2;

    for (int jt = 0; jt < ntiles; jt++) {
        if (jt + 1 < ntiles) { issue_kv(jt + 1); cp_commit(); cp_wait<1>(); }
        else { cp_wait<0>(); }
        __syncthreads();

        const uint32_t sK = sb + (8704 + (jt & 1) * 4352) * 4;
        const uint32_t* V = smu + 17408 + (jt & 1) * 4608;

        // ---- S = Q @ K^T (Q pre-scaled) ----
        float sacc[2][8][4];
        #pragma unroll
        for (int mi = 0; mi < 2; mi++)
            #pragma unroll
            for (int ni = 0; ni < 8; ni++)
                #pragma unroll
                for (int k = 0; k < 4; k++) sacc[mi][ni][k] = 0.f;

        #pragma unroll
        for (int j = 0; j < 8; j++) {
            uint32_t qa[2][4];
            #pragma unroll
            for (int mi = 0; mi < 2; mi++)
                ldsm_x4(qa[mi][0], qa[mi][1], qa[mi][2], qa[mi][3],
                        q_addr[mi] + j * 32);
            uint32_t kf[8][2];
            #pragma unroll
            for (int nip = 0; nip < 4; nip++)
                ldsm_x4(kf[2 * nip][0], kf[2 * nip][1],
                        kf[2 * nip + 1][0], kf[2 * nip + 1][1],
                        sK + k_base[nip] + j * 32);
            #pragma unroll
            for (int ni = 0; ni < 8; ni++) {
                mma_tf32(sacc[0][ni], qa[0][0], qa[0][1], qa[0][2], qa[0][3],
                         kf[ni][0], kf[ni][1]);
                mma_tf32(sacc[1][ni], qa[1][0], qa[1][1], qa[1][2], qa[1][3],
                         kf[ni][0], kf[ni][1]);
            }
        }

        // ---- causal mask on diagonal band ----
        if (jt >= 2 * bx) {
            #pragma unroll
            for (int mi = 0; mi < 2; mi++) {
                int row0 = qb + wid * 32 + mi * 16 + g;
                #pragma unroll
                for (int ni = 0; ni < 8; ni++) {
                    int col0 = jt * 64 + ni * 8 + 2 * t;
                    if (col0     > row0)     sacc[mi][ni][0] = -1e30f;
                    if (col0 + 1 > row0)     sacc[mi][ni][1] = -1e30f;
                    if (col0     > row0 + 8) sacc[mi][ni][2] = -1e30f;
                    if (col0 + 1 > row0 + 8) sacc[mi][ni][3] = -1e30f;
                }
            }
        }

        // ---- online softmax ----
        #pragma unroll
        for (int rm = 0; rm < 4; rm++) {
            const int mi = rm >> 1;
            const int c0 = (rm & 1) * 2;
            float mx = -1e30f;
            #pragma unroll
            for (int ni = 0; ni < 8; ni++)
                mx = fmaxf(mx, fmaxf(sacc[mi][ni][c0], sacc[mi][ni][c0 + 1]));
            mx = fmaxf(mx, __shfl_xor_sync(0xffffffffu, mx, 1));
            mx = fmaxf(mx, __shfl_xor_sync(0xffffffffu, mx, 2));
            float mn = fmaxf(m[rm], mx);
            float alpha = __expf(m[rm] - mn);
            float rs = 0.f;
            #pragma unroll
            for (int ni = 0; ni < 8; ni++) {
                float p0 = __expf(sacc[mi][ni][c0] - mn);
                float p1 = __expf(sacc[mi][ni][c0 + 1] - mn);
                sacc[mi][ni][c0] = p0;
                sacc[mi][ni][c0 + 1] = p1;
                rs += p0 + p1;
            }
            rs += __shfl_xor_sync(0xffffffffu, rs, 1);
            rs += __shfl_xor_sync(0xffffffffu, rs, 2);
            l[rm] = l[rm] * alpha + rs;
            m[rm] = mn;
            #pragma unroll
            for (int ni = 0; ni < 8; ni++) {
                o[mi][ni][c0] *= alpha;
                o[mi][ni][c0 + 1] *= alpha;
            }
        }

        // ---- O += P @ V via register C-frag -> A-frag transpose ----
        const int s0 = (lane & 28) | (t >> 1);
        const int s1 = s0 + 2;
        const bool odd = (t & 1);
        #pragma unroll
        for (int j = 0; j < 8; j++) {
            uint32_t pa[2][4];
            #pragma unroll
            for (int mi = 0; mi < 2; mi++) {
                float c0v = sacc[mi][j][0], c1v = sacc[mi][j][1];
                float c2v = sacc[mi][j][2], c3v = sacc[mi][j][3];
                float q00 = __shfl_sync(0xffffffffu, c0v, s0);
                float q01 = __shfl_sync(0xffffffffu, c1v, s0);
                float q10 = __shfl_sync(0xffffffffu, c2v, s0);
                float q11 = __shfl_sync(0xffffffffu, c3v, s0);
                float r00 = __shfl_sync(0xffffffffu, c0v, s1);
                float r01 = __shfl_sync(0xffffffffu, c1v, s1);
                float r10 = __shfl_sync(0xffffffffu, c2v, s1);
                float r11 = __shfl_sync(0xffffffffu, c3v, s1);
                pa[mi][0] = f2tf32(odd ? q01 : q00);
                pa[mi][1] = f2tf32(odd ? q11 : q10);
                pa[mi][2] = f2tf32(odd ? r01 : r00);
                pa[mi][3] = f2tf32(odd ? r11 : r10);
            }
            #pragma unroll
            for (int ni = 0; ni < 8; ni++) {
                uint32_t b0 = V[(j * 8 + t) * 72 + ni * 8 + g];
                uint32_t b1 = V[(j * 8 + t + 4) * 72 + ni * 8 + g];
                mma_tf32(o[0][ni], pa[0][0], pa[0][1], pa[0][2], pa[0][3], b0, b1);
                mma_tf32(o[1][ni], pa[1][0], pa[1][1], pa[1][2], pa[1][3], b0, b1);
            }
        }
        __syncthreads();
    }

    // ---- epilogue: y = O / l, tf32 bits (consumed by GEMM2) ----
    float* yb = y + (size_t)b * TSEQ * C_EMBD + h * HD;
    #pragma unroll
    for (int mi = 0; mi < 2; mi++) {
        #pragma unroll
        for (int hf = 0; hf < 2; hf++) {
            const int rm = mi * 2 + hf;
            const float inv = 1.f / l[rm];
            const int row = qb + wid * 32 + mi * 16 + hf * 8 + g;
            #pragma unroll
            for (int ni = 0; ni < 8; ni++) {
                float2 v;
                v.x = __uint_as_float(f2tf32(o[mi][ni][hf * 2] * inv));
                v.y = __uint_as_float(f2tf32(o[mi][ni][hf * 2 + 1] * inv));
                *(float2*)&yb[(size_t)row * C_EMBD + ni * 8 + 2 * t] = v;
            }
        }
    }
}

// ---------------------------------------------------------------------------
extern "C" void kernel_launch(void* const* d_in, const int* in_sizes, int n_in,
                              void* d_out, int out_size)
{
    const float* x      = (const float*)d_in[0];
    const float* W_attn = (const float*)d_in[1];
    const float* b_attn = (const float*)d_in[2];
    const float* W_proj = (const float*)d_in[3];
    const float* b_proj = (const float*)d_in[4];
    float* out = (float*)d_out;

    float *qkv, *y, *xc, *WaT, *WpT;
    cudaGetSymbolAddress((void**)&qkv, g_qkv);
    cudaGetSymbolAddress((void**)&y, g_y);
    cudaGetSymbolAddress((void**)&xc, g_xc);
    cudaGetSymbolAddress((void**)&WaT, g_WaT);
    cudaGetSymbolAddress((void**)&WpT, g_WpT);

    const int M = BATCH * TSEQ;  // 8192

    static int attr_set = 0;
    if (!attr_set) {
        cudaFuncSetAttribute(tf32_gemm_kernel,
                             cudaFuncAttributeMaxDynamicSharedMemorySize, GEMM_SMEM);
        cudaFuncSetAttribute(attn_tc_kernel,
                             cudaFuncAttributeMaxDynamicSharedMemorySize, ATT_SMEM);
        attr_set = 1;
    }

    // 0) Producers: convert x; transpose+convert weights
    {
        cvt_tf32_kernel<<<(M * C_EMBD) / 1024, 256>>>((const float4*)x, (uint4*)xc);
        dim3 g1(3 * C_EMBD / 32, C_EMBD / 32);
        transpose_kernel<<<g1, 256>>>(W_attn, WaT, C_EMBD, 3 * C_EMBD);
        dim3 g2(C_EMBD / 32, C_EMBD / 32);
        transpose_kernel<<<g2, 256>>>(W_proj, WpT, C_EMBD, C_EMBD);
    }

    // 1) QKV GEMM (epilogue: scale q, convert to tf32)
    {
        dim3 grid(3 * C_EMBD / 128, M / 128);
        tf32_gemm_kernel<<<grid, 256, GEMM_SMEM>>>(xc, WaT, b_attn, qkv,
                                                   M, 3 * C_EMBD, C_EMBD, 1);
    }

    // 2) Tensor-core flash attention
    {
        dim3 grid(TSEQ / 128, NH, BATCH);
        attn_tc_kernel<<<grid, 128, ATT_SMEM>>>(qkv, y);
    }

    // 3) Output projection (plain f32 epilogue)
    {
        dim3 grid(C_EMBD / 128, M / 128);
        tf32_gemm_kernel<<<grid, 256, GEMM_SMEM>>>(y, WpT, b_proj, out,
                                                   M, C_EMBD, C_EMBD, 0);
    }
}

// round 7
// speedup vs baseline: 4.4702x; 1.0212x over previous
#include <cuda_runtime.h>
#include <cstdint>
#include <math.h>

#define C_EMBD 1024
#define NH     16
#define HD     64
#define TSEQ   2048
#define BATCH  4

__device__ float g_qkv[(size_t)BATCH * TSEQ * 3 * C_EMBD];  // tf32 bits (q pre-scaled)
__device__ float g_y[(size_t)BATCH * TSEQ * C_EMBD];        // tf32 bits
__device__ float g_xc[(size_t)BATCH * TSEQ * C_EMBD];       // x, tf32 bits
__device__ float g_WaT[(size_t)3 * C_EMBD * C_EMBD];        // tf32 bits
__device__ float g_WpT[(size_t)C_EMBD * C_EMBD];            // tf32 bits

// ---------------------------------------------------------------------------
// Helpers
// ---------------------------------------------------------------------------
__device__ __forceinline__ uint32_t smem_u32(const void* p) {
    uint32_t a;
    asm("{ .reg .u64 t; cvta.to.shared.u64 t, %1; cvt.u32.u64 %0, t; }" : "=r"(a) : "l"(p));
    return a;
}
__device__ __forceinline__ void cp_async16(uint32_t dst, const void* src) {
    asm volatile("cp.async.cg.shared.global [%0], [%1], 16;" :: "r"(dst), "l"(src) : "memory");
}
__device__ __forceinline__ void cp_commit() {
    asm volatile("cp.async.commit_group;" ::: "memory");
}
template <int N>
__device__ __forceinline__ void cp_wait() {
    asm volatile("cp.async.wait_group %0;" :: "n"(N) : "memory");
}
__device__ __forceinline__ uint32_t f2tf32(float x) {
    uint32_t y;
    asm("cvt.rna.tf32.f32 %0, %1;" : "=r"(y) : "f"(x));
    return y;
}
__device__ __forceinline__ void mma_tf32(float* c, uint32_t a0, uint32_t a1,
                                         uint32_t a2, uint32_t a3,
                                         uint32_t b0, uint32_t b1) {
    asm volatile(
        "mma.sync.aligned.m16n8k8.row.col.f32.tf32.tf32.f32 "
        "{%0,%1,%2,%3}, {%4,%5,%6,%7}, {%8,%9}, {%0,%1,%2,%3};"
        : "+f"(c[0]), "+f"(c[1]), "+f"(c[2]), "+f"(c[3])
        : "r"(a0), "r"(a1), "r"(a2), "r"(a3), "r"(b0), "r"(b1));
}
__device__ __forceinline__ void ldsm_x4(uint32_t& r0, uint32_t& r1,
                                        uint32_t& r2, uint32_t& r3, uint32_t addr) {
    asm volatile("ldmatrix.sync.aligned.m8n8.x4.shared.b16 {%0,%1,%2,%3}, [%4];"
                 : "=r"(r0), "=r"(r1), "=r"(r2), "=r"(r3) : "r"(addr));
}

// ---------------------------------------------------------------------------
// Elementwise tf32 convert (for x)
// ---------------------------------------------------------------------------
__global__ __launch_bounds__(256)
void cvt_tf32_kernel(const float4* __restrict__ in, uint4* __restrict__ out)
{
    int i = blockIdx.x * 256 + threadIdx.x;
    float4 v = in[i];
    uint4 u;
    u.x = f2tf32(v.x); u.y = f2tf32(v.y); u.z = f2tf32(v.z); u.w = f2tf32(v.w);
    out[i] = u;
}

// ---------------------------------------------------------------------------
// Weight transpose + tf32 convert: W[R][Ncols] -> WT[Ncols][R] (tf32 bits)
// ---------------------------------------------------------------------------
__global__ __launch_bounds__(256)
void transpose_kernel(const float* __restrict__ W, float* __restrict__ WT,
                      int R, int Ncols)
{
    __shared__ float t[32][33];
    const int bx = blockIdx.x * 32;
    const int by = blockIdx.y * 32;
    const int tx = threadIdx.x & 31;
    const int ty8 = threadIdx.x >> 5;
    #pragma unroll
    for (int i = 0; i < 32; i += 8)
        t[ty8 + i][tx] = W[(size_t)(by + ty8 + i) * Ncols + bx + tx];
    __syncthreads();
    #pragma unroll
    for (int i = 0; i < 32; i += 8)
        WT[(size_t)(bx + ty8 + i) * R + by + tx] =
            __uint_as_float(f2tf32(t[tx][ty8 + i]));
}

// ---------------------------------------------------------------------------
// tf32 mma.sync GEMM with bias. Pre-converted tf32 inputs.
// CTA tile 128x256, BK=32, 8 warps (2x4), warp tile 64x64.
// 4 smem buffers (192 KB), prefetch distance 2, one barrier/stage, ldmatrix.
// ---------------------------------------------------------------------------
#define GEMM_SMEM 196608

__global__ __launch_bounds__(256, 1)
void tf32_gemm_kernel(const float* __restrict__ A,
                      const float* __restrict__ BT,
                      const float* __restrict__ bias,
                      float* __restrict__ Cm,
                      int M, int N, int K, int mode)
{
    extern __shared__ char smem[];
    const uint32_t sb = smem_u32(smem);

    const int tid = threadIdx.x;
    const int wid = tid >> 5;
    const int lane = tid & 31;
    const int g = lane >> 2;
    const int t = lane & 3;
    const int wm = wid >> 2;      // 0..1
    const int wn = wid & 3;       // 0..3

    const int bm0 = blockIdx.y * 128;
    const int bn0 = blockIdx.x * 256;
    const int NS = K >> 5;

    // ldmatrix per-lane geometry
    const int a_lrow = (lane & 7) | ((lane & 8)  ? 8 : 0);
    const int a_sel  = lane >> 4;
    const int b_lrow = (lane & 7) | ((lane & 16) ? 8 : 0);
    const int b_sel  = (lane >> 3) & 1;
    uint32_t a_off[4], a_rot[4], b_off[4], b_rot[4];
    #pragma unroll
    for (int mi = 0; mi < 4; mi++) {
        int row = wm * 64 + mi * 16 + a_lrow;
        a_off[mi] = (uint32_t)row << 7;           // row * 128 bytes
        a_rot[mi] = row & 7;
    }
    #pragma unroll
    for (int nip = 0; nip < 4; nip++) {
        int row = wn * 64 + nip * 16 + b_lrow;
        b_off[nip] = (uint32_t)row << 7;
        b_rot[nip] = row & 7;
    }

    float acc[4][8][4];
    #pragma unroll
    for (int i = 0; i < 4; i++)
        #pragma unroll
        for (int j = 0; j < 8; j++)
            #pragma unroll
            for (int r = 0; r < 4; r++) acc[i][j][r] = 0.f;

    auto load_stage = [&](int s) {
        const int k0 = s * 32;
        const int buf = s & 3;
        const uint32_t sA = sb + buf * 16384;
        const uint32_t sB = sb + 65536 + buf * 32768;
        #pragma unroll
        for (int it = 0; it < 4; it++) {          // A: 1024 float4
            int idx = it * 256 + tid;
            int r = idx >> 3, ck = idx & 7;
            uint32_t d = sA + r * 128 + ((((ck + r) & 7)) << 4);
            cp_async16(d, &A[(size_t)(bm0 + r) * K + k0 + ck * 4]);
        }
        #pragma unroll
        for (int it = 0; it < 8; it++) {          // B: 2048 float4
            int idx = it * 256 + tid;
            int r = idx >> 3, ck = idx & 7;
            uint32_t d = sB + r * 128 + ((((ck + r) & 7)) << 4);
            cp_async16(d, &BT[(size_t)(bn0 + r) * K + k0 + ck * 4]);
        }
        cp_commit();
    };

    load_stage(0);
    load_stage(1);

    for (int s = 0; s < NS; s++) {
        if (s + 2 < NS) { load_stage(s + 2); cp_wait<2>(); }
        else if (s + 1 < NS) { cp_wait<1>(); }
        else { cp_wait<0>(); }
        __syncthreads();

        const int buf = s & 3;
        const uint32_t sA = sb + buf * 16384;
        const uint32_t sB = sb + 65536 + buf * 32768;

        #pragma unroll
        for (int ks = 0; ks < 4; ks++) {
            const int ckA = 2 * ks + a_sel;
            const int ckB = 2 * ks + b_sel;
            uint32_t afr[4][4];
            #pragma unroll
            for (int mi = 0; mi < 4; mi++)
                ldsm_x4(afr[mi][0], afr[mi][1], afr[mi][2], afr[mi][3],
                        sA + a_off[mi] + (((ckA + a_rot[mi]) & 7) << 4));
            uint32_t bfr[8][2];
            #pragma unroll
            for (int nip = 0; nip < 4; nip++)
                ldsm_x4(bfr[2 * nip][0], bfr[2 * nip][1],
                        bfr[2 * nip + 1][0], bfr[2 * nip + 1][1],
                        sB + b_off[nip] + (((ckB + b_rot[nip]) & 7) << 4));
            #pragma unroll
            for (int mi = 0; mi < 4; mi++)
                #pragma unroll
                for (int ni = 0; ni < 8; ni++)
                    mma_tf32(acc[mi][ni],
                             afr[mi][0], afr[mi][1], afr[mi][2], afr[mi][3],
                             bfr[ni][0], bfr[ni][1]);
        }
    }

    #pragma unroll
    for (int mi = 0; mi < 4; mi++) {
        #pragma unroll
        for (int ni = 0; ni < 8; ni++) {
            int row0 = bm0 + wm * 64 + mi * 16 + g;
            int col  = bn0 + wn * 64 + ni * 8 + 2 * t;
            float bx = bias[col], by = bias[col + 1];
            float v00 = acc[mi][ni][0] + bx, v01 = acc[mi][ni][1] + by;
            float v10 = acc[mi][ni][2] + bx, v11 = acc[mi][ni][3] + by;
            if (mode == 1) {
                if (col < C_EMBD) {
                    v00 *= 0.125f; v01 *= 0.125f; v10 *= 0.125f; v11 *= 0.125f;
                }
                v00 = __uint_as_float(f2tf32(v00));
                v01 = __uint_as_float(f2tf32(v01));
                v10 = __uint_as_float(f2tf32(v10));
                v11 = __uint_as_float(f2tf32(v11));
            }
            float2 w0 = {v00, v01}, w1 = {v10, v11};
            *(float2*)&Cm[(size_t)row0 * N + col] = w0;
            *(float2*)&Cm[(size_t)(row0 + 8) * N + col] = w1;
        }
    }
}

// ---------------------------------------------------------------------------
// Tensor-core flash attention (tf32), causal. (unchanged from R6)
// ---------------------------------------------------------------------------
#define ATT_SMEM 106496

__global__ __launch_bounds__(128, 1)
void attn_tc_kernel(const float* __restrict__ qkv, float* __restrict__ y)
{
    extern __shared__ uint32_t smu[];
    const uint32_t sb = smem_u32(smu);

    const int tid = threadIdx.x;
    const int wid = tid >> 5;
    const int lane = tid & 31;
    const int g = lane >> 2;
    const int t = lane & 3;
    const int bx = (gridDim.x - 1) - blockIdx.x;   // heavy tiles first
    const int h = blockIdx.y;
    const int b = blockIdx.z;
    const int qb = bx * 128;

    const float* base = qkv + (size_t)b * TSEQ * (3 * C_EMBD) + h * HD;

    const int a_lrow = (lane & 7) | ((lane & 8)  ? 8 : 0);
    const int a_sel  = lane >> 4;
    const int b_lrow = (lane & 7) | ((lane & 16) ? 8 : 0);
    const int b_sel  = (lane >> 3) & 1;
    uint32_t q_addr[2];
    #pragma unroll
    for (int mi = 0; mi < 2; mi++) {
        int row = wid * 32 + mi * 16 + a_lrow;
        q_addr[mi] = sb + row * 272 + a_sel * 16;
    }
    uint32_t k_base[4];
    #pragma unroll
    for (int nip = 0; nip < 4; nip++) {
        int row = nip * 16 + b_lrow;
        k_base[nip] = row * 272 + b_sel * 16;
    }

    auto issue_kv = [&](int jt) {
        const uint32_t sk = sb + (8704 + (jt & 1) * 4352) * 4;
        const uint32_t sv = sb + (17408 + (jt & 1) * 4608) * 4;
        #pragma unroll
        for (int it = 0; it < 8; it++) {
            int idx = it * 128 + tid;
            int r = idx >> 4, c4 = idx & 15;
            const float* rp = &base[(size_t)(jt * 64 + r) * (3 * C_EMBD) + c4 * 4];
            cp_async16(sk + (r * 68 + c4 * 4) * 4, rp + C_EMBD);
            cp_async16(sv + (r * 72 + c4 * 4) * 4, rp + 2 * C_EMBD);
        }
    };

    #pragma unroll
    for (int it = 0; it < 16; it++) {
        int idx = it * 128 + tid;
        int r = idx >> 4, c4 = idx & 15;
        cp_async16(sb + (r * 68 + c4 * 4) * 4,
                   &base[(size_t)(qb + r) * (3 * C_EMBD) + c4 * 4]);
    }
    issue_kv(0);
    cp_commit();

    float m[4], l[4], o[2][8][4];
    #pragma unroll
    for (int rm = 0; rm < 4; rm++) { m[rm] = -1e30f; l[rm] = 0.f; }
    #pragma unroll
    for (int mi = 0; mi < 2; mi++)
        #pragma unroll
        for (int ni = 0; ni < 8; ni++)
            #pragma unroll
            for (int k = 0; k < 4; k++) o[mi][ni][k] = 0.f;

    const int ntiles = 2 * bx + 2;

    for (int jt = 0; jt < ntiles; jt++) {
        if (jt + 1 < ntiles) { issue_kv(jt + 1); cp_commit(); cp_wait<1>(); }
        else { cp_wait<0>(); }
        __syncthreads();

        const uint32_t sK = sb + (8704 + (jt & 1) * 4352) * 4;
        const uint32_t* V = smu + 17408 + (jt & 1) * 4608;

        float sacc[2][8][4];
        #pragma unroll
        for (int mi = 0; mi < 2; mi++)
            #pragma unroll
            for (int ni = 0; ni < 8; ni++)
                #pragma unroll
                for (int k = 0; k < 4; k++) sacc[mi][ni][k] = 0.f;

        #pragma unroll
        for (int j = 0; j < 8; j++) {
            uint32_t qa[2][4];
            #pragma unroll
            for (int mi = 0; mi < 2; mi++)
                ldsm_x4(qa[mi][0], qa[mi][1], qa[mi][2], qa[mi][3],
                        q_addr[mi] + j * 32);
            uint32_t kf[8][2];
            #pragma unroll
            for (int nip = 0; nip < 4; nip++)
                ldsm_x4(kf[2 * nip][0], kf[2 * nip][1],
                        kf[2 * nip + 1][0], kf[2 * nip + 1][1],
                        sK + k_base[nip] + j * 32);
            #pragma unroll
            for (int ni = 0; ni < 8; ni++) {
                mma_tf32(sacc[0][ni], qa[0][0], qa[0][1], qa[0][2], qa[0][3],
                         kf[ni][0], kf[ni][1]);
                mma_tf32(sacc[1][ni], qa[1][0], qa[1][1], qa[1][2], qa[1][3],
                         kf[ni][0], kf[ni][1]);
            }
        }

        if (jt >= 2 * bx) {
            #pragma unroll
            for (int mi = 0; mi < 2; mi++) {
                int row0 = qb + wid * 32 + mi * 16 + g;
                #pragma unroll
                for (int ni = 0; ni < 8; ni++) {
                    int col0 = jt * 64 + ni * 8 + 2 * t;
                    if (col0     > row0)     sacc[mi][ni][0] = -1e30f;
                    if (col0 + 1 > row0)     sacc[mi][ni][1] = -1e30f;
                    if (col0     > row0 + 8) sacc[mi][ni][2] = -1e30f;
                    if (col0 + 1 > row0 + 8) sacc[mi][ni][3] = -1e30f;
                }
            }
        }

        #pragma unroll
        for (int rm = 0; rm < 4; rm++) {
            const int mi = rm >> 1;
            const int c0 = (rm & 1) * 2;
            float mx = -1e30f;
            #pragma unroll
            for (int ni = 0; ni < 8; ni++)
                mx = fmaxf(mx, fmaxf(sacc[mi][ni][c0], sacc[mi][ni][c0 + 1]));
            mx = fmaxf(mx, __shfl_xor_sync(0xffffffffu, mx, 1));
            mx = fmaxf(mx, __shfl_xor_sync(0xffffffffu, mx, 2));
            float mn = fmaxf(m[rm], mx);
            float alpha = __expf(m[rm] - mn);
            float rs = 0.f;
            #pragma unroll
            for (int ni = 0; ni < 8; ni++) {
                float p0 = __expf(sacc[mi][ni][c0] - mn);
                float p1 = __expf(sacc[mi][ni][c0 + 1] - mn);
                sacc[mi][ni][c0] = p0;
                sacc[mi][ni][c0 + 1] = p1;
                rs += p0 + p1;
            }
            rs += __shfl_xor_sync(0xffffffffu, rs, 1);
            rs += __shfl_xor_sync(0xffffffffu, rs, 2);
            l[rm] = l[rm] * alpha + rs;
            m[rm] = mn;
            #pragma unroll
            for (int ni = 0; ni < 8; ni++) {
                o[mi][ni][c0] *= alpha;
                o[mi][ni][c0 + 1] *= alpha;
            }
        }

        const int s0 = (lane & 28) | (t >> 1);
        const int s1 = s0 + 2;
        const bool odd = (t & 1);
        #pragma unroll
        for (int j = 0; j < 8; j++) {
            uint32_t pa[2][4];
            #pragma unroll
            for (int mi = 0; mi < 2; mi++) {
                float c0v = sacc[mi][j][0], c1v = sacc[mi][j][1];
                float c2v = sacc[mi][j][2], c3v = sacc[mi][j][3];
                float q00 = __shfl_sync(0xffffffffu, c0v, s0);
                float q01 = __shfl_sync(0xffffffffu, c1v, s0);
                float q10 = __shfl_sync(0xffffffffu, c2v, s0);
                float q11 = __shfl_sync(0xffffffffu, c3v, s0);
                float r00 = __shfl_sync(0xffffffffu, c0v, s1);
                float r01 = __shfl_sync(0xffffffffu, c1v, s1);
                float r10 = __shfl_sync(0xffffffffu, c2v, s1);
                float r11 = __shfl_sync(0xffffffffu, c3v, s1);
                pa[mi][0] = f2tf32(odd ? q01 : q00);
                pa[mi][1] = f2tf32(odd ? q11 : q10);
                pa[mi][2] = f2tf32(odd ? r01 : r00);
                pa[mi][3] = f2tf32(odd ? r11 : r10);
            }
            #pragma unroll
            for (int ni = 0; ni < 8; ni++) {
                uint32_t b0 = V[(j * 8 + t) * 72 + ni * 8 + g];
                uint32_t b1 = V[(j * 8 + t + 4) * 72 + ni * 8 + g];
                mma_tf32(o[0][ni], pa[0][0], pa[0][1], pa[0][2], pa[0][3], b0, b1);
                mma_tf32(o[1][ni], pa[1][0], pa[1][1], pa[1][2], pa[1][3], b0, b1);
            }
        }
        __syncthreads();
    }

    float* yb = y + (size_t)b * TSEQ * C_EMBD + h * HD;
    #pragma unroll
    for (int mi = 0; mi < 2; mi++) {
        #pragma unroll
        for (int hf = 0; hf < 2; hf++) {
            const int rm = mi * 2 + hf;
            const float inv = 1.f / l[rm];
            const int row = qb + wid * 32 + mi * 16 + hf * 8 + g;
            #pragma unroll
            for (int ni = 0; ni < 8; ni++) {
                float2 v;
                v.x = __uint_as_float(f2tf32(o[mi][ni][hf * 2] * inv));
                v.y = __uint_as_float(f2tf32(o[mi][ni][hf * 2 + 1] * inv));
                *(float2*)&yb[(size_t)row * C_EMBD + ni * 8 + 2 * t] = v;
            }
        }
    }
}

// ---------------------------------------------------------------------------
extern "C" void kernel_launch(void* const* d_in, const int* in_sizes, int n_in,
                              void* d_out, int out_size)
{
    const float* x      = (const float*)d_in[0];
    const float* W_attn = (const float*)d_in[1];
    const float* b_attn = (const float*)d_in[2];
    const float* W_proj = (const float*)d_in[3];
    const float* b_proj = (const float*)d_in[4];
    float* out = (float*)d_out;

    float *qkv, *y, *xc, *WaT, *WpT;
    cudaGetSymbolAddress((void**)&qkv, g_qkv);
    cudaGetSymbolAddress((void**)&y, g_y);
    cudaGetSymbolAddress((void**)&xc, g_xc);
    cudaGetSymbolAddress((void**)&WaT, g_WaT);
    cudaGetSymbolAddress((void**)&WpT, g_WpT);

    const int M = BATCH * TSEQ;  // 8192

    static int attr_set = 0;
    if (!attr_set) {
        cudaFuncSetAttribute(tf32_gemm_kernel,
                             cudaFuncAttributeMaxDynamicSharedMemorySize, GEMM_SMEM);
        cudaFuncSetAttribute(attn_tc_kernel,
                             cudaFuncAttributeMaxDynamicSharedMemorySize, ATT_SMEM);
        attr_set = 1;
    }

    // 0) Producers: convert x; transpose+convert weights
    {
        cvt_tf32_kernel<<<(M * C_EMBD) / 1024, 256>>>((const float4*)x, (uint4*)xc);
        dim3 g1(3 * C_EMBD / 32, C_EMBD / 32);
        transpose_kernel<<<g1, 256>>>(W_attn, WaT, C_EMBD, 3 * C_EMBD);
        dim3 g2(C_EMBD / 32, C_EMBD / 32);
        transpose_kernel<<<g2, 256>>>(W_proj, WpT, C_EMBD, C_EMBD);
    }

    // 1) QKV GEMM (epilogue: scale q, convert to tf32)
    {
        dim3 grid(3 * C_EMBD / 256, M / 128);
        tf32_gemm_kernel<<<grid, 256, GEMM_SMEM>>>(xc, WaT, b_attn, qkv,
                                                   M, 3 * C_EMBD, C_EMBD, 1);
    }

    // 2) Tensor-core flash attention
    {
        dim3 grid(TSEQ / 128, NH, BATCH);
        attn_tc_kernel<<<grid, 128, ATT_SMEM>>>(qkv, y);
    }

    // 3) Output projection (plain f32 epilogue)
    {
        dim3 grid(C_EMBD / 256, M / 128);
        tf32_gemm_kernel<<<grid, 256, GEMM_SMEM>>>(y, WpT, b_proj, out,
                                                   M, C_EMBD, C_EMBD, 0);
    }
}

// round 8
// speedup vs baseline: 8.2115x; 1.8369x over previous
#include <cuda_runtime.h>
#include <cuda_fp16.h>
#include <cstdint>
#include <math.h>

#define C_EMBD 1024
#define NH     16
#define HD     64
#define TSEQ   2048
#define BATCH  4

__device__ __half g_qkv[(size_t)BATCH * TSEQ * 3 * C_EMBD];  // fp16 (q pre-scaled)
__device__ __half g_y[(size_t)BATCH * TSEQ * C_EMBD];        // fp16
__device__ __half g_xc[(size_t)BATCH * TSEQ * C_EMBD];       // x, fp16
__device__ __half g_WaT[(size_t)3 * C_EMBD * C_EMBD];        // fp16
__device__ __half g_WpT[(size_t)C_EMBD * C_EMBD];            // fp16

// ---------------------------------------------------------------------------
// Helpers
// ---------------------------------------------------------------------------
__device__ __forceinline__ uint32_t smem_u32(const void* p) {
    uint32_t a;
    asm("{ .reg .u64 t; cvta.to.shared.u64 t, %1; cvt.u32.u64 %0, t; }" : "=r"(a) : "l"(p));
    return a;
}
__device__ __forceinline__ void cp_async16(uint32_t dst, const void* src) {
    asm volatile("cp.async.cg.shared.global [%0], [%1], 16;" :: "r"(dst), "l"(src) : "memory");
}
__device__ __forceinline__ void cp_commit() {
    asm volatile("cp.async.commit_group;" ::: "memory");
}
template <int N>
__device__ __forceinline__ void cp_wait() {
    asm volatile("cp.async.wait_group %0;" :: "n"(N) : "memory");
}
__device__ __forceinline__ uint32_t pack_h2(float a, float b) {
    __half2 h = __floats2half2_rn(a, b);
    return *(uint32_t*)&h;
}
__device__ __forceinline__ void mma_f16(float* c, uint32_t a0, uint32_t a1,
                                        uint32_t a2, uint32_t a3,
                                        uint32_t b0, uint32_t b1) {
    asm volatile(
        "mma.sync.aligned.m16n8k16.row.col.f32.f16.f16.f32 "
        "{%0,%1,%2,%3}, {%4,%5,%6,%7}, {%8,%9}, {%0,%1,%2,%3};"
        : "+f"(c[0]), "+f"(c[1]), "+f"(c[2]), "+f"(c[3])
        : "r"(a0), "r"(a1), "r"(a2), "r"(a3), "r"(b0), "r"(b1));
}
__device__ __forceinline__ void ldsm_x4(uint32_t& r0, uint32_t& r1,
                                        uint32_t& r2, uint32_t& r3, uint32_t addr) {
    asm volatile("ldmatrix.sync.aligned.m8n8.x4.shared.b16 {%0,%1,%2,%3}, [%4];"
                 : "=r"(r0), "=r"(r1), "=r"(r2), "=r"(r3) : "r"(addr));
}
__device__ __forceinline__ void ldsm_x4_t(uint32_t& r0, uint32_t& r1,
                                          uint32_t& r2, uint32_t& r3, uint32_t addr) {
    asm volatile("ldmatrix.sync.aligned.m8n8.x4.trans.shared.b16 {%0,%1,%2,%3}, [%4];"
                 : "=r"(r0), "=r"(r1), "=r"(r2), "=r"(r3) : "r"(addr));
}

// ---------------------------------------------------------------------------
// Elementwise fp16 convert (for x): 4 floats -> 4 halves per thread
// ---------------------------------------------------------------------------
__global__ __launch_bounds__(256)
void cvt_f16_kernel(const float4* __restrict__ in, uint2* __restrict__ out)
{
    int i = blockIdx.x * 256 + threadIdx.x;
    float4 v = in[i];
    out[i] = make_uint2(pack_h2(v.x, v.y), pack_h2(v.z, v.w));
}

// ---------------------------------------------------------------------------
// Weight transpose + fp16 convert: W[R][Ncols] (f32) -> WT[Ncols][R] (f16)
// ---------------------------------------------------------------------------
__global__ __launch_bounds__(256)
void transpose_kernel(const float* __restrict__ W, __half* __restrict__ WT,
                      int R, int Ncols)
{
    __shared__ float t[32][33];
    const int bx = blockIdx.x * 32;
    const int by = blockIdx.y * 32;
    const int tx = threadIdx.x & 31;
    const int ty8 = threadIdx.x >> 5;
    #pragma unroll
    for (int i = 0; i < 32; i += 8)
        t[ty8 + i][tx] = W[(size_t)(by + ty8 + i) * Ncols + bx + tx];
    __syncthreads();
    #pragma unroll
    for (int i = 0; i < 32; i += 8)
        WT[(size_t)(bx + ty8 + i) * R + by + tx] = __float2half_rn(t[tx][ty8 + i]);
}

// ---------------------------------------------------------------------------
// fp16 mma.sync GEMM with bias: C[M,N] = A[M,K] @ BT[N,K]^T + bias[N]
// CTA tile 128x256, BK=64 (128B rows), 8 warps (2x4), warp tile 64x64.
// 4 smem buffers, prefetch distance 2, one barrier/stage, ldmatrix fragments.
// mode 0: f32 out. mode 1: f16 out, cols<C_EMBD scaled by 0.125 (q).
// ---------------------------------------------------------------------------
#define GEMM_SMEM 196608

__global__ __launch_bounds__(256, 1)
void f16_gemm_kernel(const __half* __restrict__ A,
                     const __half* __restrict__ BT,
                     const float* __restrict__ bias,
                     void* __restrict__ Cm,
                     int M, int N, int K, int mode)
{
    extern __shared__ char smem[];
    const uint32_t sb = smem_u32(smem);

    const int tid = threadIdx.x;
    const int wid = tid >> 5;
    const int lane = tid & 31;
    const int g = lane >> 2;
    const int t = lane & 3;
    const int wm = wid >> 2;      // 0..1
    const int wn = wid & 3;       // 0..3

    const int bm0 = blockIdx.y * 128;
    const int bn0 = blockIdx.x * 256;
    const int NS = K >> 6;        // BK=64

    // ldmatrix per-lane geometry (rows are 128B = 8 chunks of 16B, rotated)
    const int a_lrow = (lane & 7) | ((lane & 8)  ? 8 : 0);
    const int a_sel  = lane >> 4;
    const int b_lrow = (lane & 7) | ((lane & 16) ? 8 : 0);
    const int b_sel  = (lane >> 3) & 1;
    uint32_t a_off[4], a_rot[4], b_off[4], b_rot[4];
    #pragma unroll
    for (int mi = 0; mi < 4; mi++) {
        int row = wm * 64 + mi * 16 + a_lrow;
        a_off[mi] = (uint32_t)row << 7;
        a_rot[mi] = row & 7;
    }
    #pragma unroll
    for (int nip = 0; nip < 4; nip++) {
        int row = wn * 64 + nip * 16 + b_lrow;
        b_off[nip] = (uint32_t)row << 7;
        b_rot[nip] = row & 7;
    }

    float acc[4][8][4];
    #pragma unroll
    for (int i = 0; i < 4; i++)
        #pragma unroll
        for (int j = 0; j < 8; j++)
            #pragma unroll
            for (int r = 0; r < 4; r++) acc[i][j][r] = 0.f;

    auto load_stage = [&](int s) {
        const int k0 = s * 64;
        const int buf = s & 3;
        const uint32_t sA = sb + buf * 16384;
        const uint32_t sB = sb + 65536 + buf * 32768;
        #pragma unroll
        for (int it = 0; it < 4; it++) {          // A: 1024 chunks of 16B
            int idx = it * 256 + tid;
            int r = idx >> 3, ck = idx & 7;
            uint32_t d = sA + r * 128 + ((((ck + r) & 7)) << 4);
            cp_async16(d, &A[(size_t)(bm0 + r) * K + k0 + ck * 8]);
        }
        #pragma unroll
        for (int it = 0; it < 8; it++) {          // B: 2048 chunks
            int idx = it * 256 + tid;
            int r = idx >> 3, ck = idx & 7;
            uint32_t d = sB + r * 128 + ((((ck + r) & 7)) << 4);
            cp_async16(d, &BT[(size_t)(bn0 + r) * K + k0 + ck * 8]);
        }
        cp_commit();
    };

    load_stage(0);
    load_stage(1);

    for (int s = 0; s < NS; s++) {
        if (s + 2 < NS) { load_stage(s + 2); cp_wait<2>(); }
        else if (s + 1 < NS) { cp_wait<1>(); }
        else { cp_wait<0>(); }
        __syncthreads();

        const int buf = s & 3;
        const uint32_t sA = sb + buf * 16384;
        const uint32_t sB = sb + 65536 + buf * 32768;

        #pragma unroll
        for (int ks = 0; ks < 4; ks++) {          // 4 x k16 slices
            const int ckA = 2 * ks + a_sel;
            const int ckB = 2 * ks + b_sel;
            uint32_t afr[4][4];
            #pragma unroll
            for (int mi = 0; mi < 4; mi++)
                ldsm_x4(afr[mi][0], afr[mi][1], afr[mi][2], afr[mi][3],
                        sA + a_off[mi] + (((ckA + a_rot[mi]) & 7) << 4));
            uint32_t bfr[8][2];
            #pragma unroll
            for (int nip = 0; nip < 4; nip++)
                ldsm_x4(bfr[2 * nip][0], bfr[2 * nip][1],
                        bfr[2 * nip + 1][0], bfr[2 * nip + 1][1],
                        sB + b_off[nip] + (((ckB + b_rot[nip]) & 7) << 4));
            #pragma unroll
            for (int mi = 0; mi < 4; mi++)
                #pragma unroll
                for (int ni = 0; ni < 8; ni++)
                    mma_f16(acc[mi][ni],
                            afr[mi][0], afr[mi][1], afr[mi][2], afr[mi][3],
                            bfr[ni][0], bfr[ni][1]);
        }
    }

    #pragma unroll
    for (int mi = 0; mi < 4; mi++) {
        #pragma unroll
        for (int ni = 0; ni < 8; ni++) {
            int row0 = bm0 + wm * 64 + mi * 16 + g;
            int col  = bn0 + wn * 64 + ni * 8 + 2 * t;
            float bx = bias[col], by = bias[col + 1];
            float v00 = acc[mi][ni][0] + bx, v01 = acc[mi][ni][1] + by;
            float v10 = acc[mi][ni][2] + bx, v11 = acc[mi][ni][3] + by;
            if (mode == 1) {
                if (col < C_EMBD) {
                    v00 *= 0.125f; v01 *= 0.125f; v10 *= 0.125f; v11 *= 0.125f;
                }
                __half* Ch = (__half*)Cm;
                *(uint32_t*)&Ch[(size_t)row0 * N + col] = pack_h2(v00, v01);
                *(uint32_t*)&Ch[(size_t)(row0 + 8) * N + col] = pack_h2(v10, v11);
            } else {
                float* Cf = (float*)Cm;
                float2 w0 = {v00, v01}, w1 = {v10, v11};
                *(float2*)&Cf[(size_t)row0 * N + col] = w0;
                *(float2*)&Cf[(size_t)(row0 + 8) * N + col] = w1;
            }
        }
    }
}

// ---------------------------------------------------------------------------
// fp16 tensor-core flash attention, causal. Q/K via ldmatrix, V via
// ldmatrix.trans; P fragments come directly from C fragments (no shuffles).
// smem bytes: Q[128][72h] @0 (18432), K 2x[64][72h] @18432, V 2x @36864.
// Total 55296 B.
// ---------------------------------------------------------------------------
#define ATT_SMEM 55296

__global__ __launch_bounds__(128, 1)
void attn_tc_kernel(const __half* __restrict__ qkv, __half* __restrict__ y)
{
    extern __shared__ char smc[];
    const uint32_t sb = smem_u32(smc);

    const int tid = threadIdx.x;
    const int wid = tid >> 5;
    const int lane = tid & 31;
    const int g = lane >> 2;
    const int t = lane & 3;
    const int bx = (gridDim.x - 1) - blockIdx.x;   // heavy tiles first
    const int h = blockIdx.y;
    const int b = blockIdx.z;
    const int qb = bx * 128;

    const __half* base = qkv + (size_t)b * TSEQ * (3 * C_EMBD) + h * HD;

    // ldmatrix geometry (row stride 144 B; quad = (row + ck) mod 8 conflict-free)
    const int a_lrow = (lane & 7) | ((lane & 8)  ? 8 : 0);
    const int a_sel  = lane >> 4;
    const int b_lrow = (lane & 7) | ((lane & 16) ? 8 : 0);
    const int b_sel  = (lane >> 3) & 1;
    const int v_lrow = (lane & 7) | ((lane & 8) ? 8 : 0);
    const int v_c16  = (lane & 16) ? 16 : 0;

    uint32_t q_addr[2];
    #pragma unroll
    for (int mi = 0; mi < 2; mi++)
        q_addr[mi] = sb + (wid * 32 + mi * 16 + a_lrow) * 144 + a_sel * 16;
    uint32_t k_off[4];
    #pragma unroll
    for (int nip = 0; nip < 4; nip++)
        k_off[nip] = (nip * 16 + b_lrow) * 144 + b_sel * 16;
    uint32_t v_off[4];
    #pragma unroll
    for (int nip = 0; nip < 4; nip++)
        v_off[nip] = v_lrow * 144 + nip * 32 + v_c16;

    auto issue_kv = [&](int jt) {
        const uint32_t sk = sb + 18432 + (jt & 1) * 9216;
        const uint32_t sv = sb + 36864 + (jt & 1) * 9216;
        #pragma unroll
        for (int it = 0; it < 4; it++) {           // K: 512 chunks
            int idx = it * 128 + tid;
            int r = idx >> 3, ck = idx & 7;
            cp_async16(sk + r * 144 + ck * 16,
                       base + (size_t)(jt * 64 + r) * (3 * C_EMBD) + C_EMBD + ck * 8);
        }
        #pragma unroll
        for (int it = 0; it < 4; it++) {           // V: 512 chunks
            int idx = it * 128 + tid;
            int r = idx >> 3, ck = idx & 7;
            cp_async16(sv + r * 144 + ck * 16,
                       base + (size_t)(jt * 64 + r) * (3 * C_EMBD) + 2 * C_EMBD + ck * 8);
        }
    };

    // Prologue: Q tile (128 rows x 8 chunks) + KV tile 0
    #pragma unroll
    for (int it = 0; it < 8; it++) {
        int idx = it * 128 + tid;
        int r = idx >> 3, ck = idx & 7;
        cp_async16(sb + r * 144 + ck * 16,
                   base + (size_t)(qb + r) * (3 * C_EMBD) + ck * 8);
    }
    issue_kv(0);
    cp_commit();

    float m[4], l[4], o[2][8][4];
    #pragma unroll
    for (int rm = 0; rm < 4; rm++) { m[rm] = -1e30f; l[rm] = 0.f; }
    #pragma unroll
    for (int mi = 0; mi < 2; mi++)
        #pragma unroll
        for (int ni = 0; ni < 8; ni++)
            #pragma unroll
            for (int k = 0; k < 4; k++) o[mi][ni][k] = 0.f;

    const int ntiles = 2 * bx + 2;

    for (int jt = 0; jt < ntiles; jt++) {
        if (jt + 1 < ntiles) { issue_kv(jt + 1); cp_commit(); cp_wait<1>(); }
        else { cp_wait<0>(); }
        __syncthreads();

        const uint32_t sK = sb + 18432 + (jt & 1) * 9216;
        const uint32_t sV = sb + 36864 + (jt & 1) * 9216;

        // ---- S = Q @ K^T (Q pre-scaled), 4 k16 slices over HD=64 ----
        float sacc[2][8][4];
        #pragma unroll
        for (int mi = 0; mi < 2; mi++)
            #pragma unroll
            for (int ni = 0; ni < 8; ni++)
                #pragma unroll
                for (int k = 0; k < 4; k++) sacc[mi][ni][k] = 0.f;

        #pragma unroll
        for (int ks = 0; ks < 4; ks++) {
            uint32_t qa[2][4];
            #pragma unroll
            for (int mi = 0; mi < 2; mi++)
                ldsm_x4(qa[mi][0], qa[mi][1], qa[mi][2], qa[mi][3],
                        q_addr[mi] + ks * 32);
            uint32_t kf[8][2];
            #pragma unroll
            for (int nip = 0; nip < 4; nip++)
                ldsm_x4(kf[2 * nip][0], kf[2 * nip][1],
                        kf[2 * nip + 1][0], kf[2 * nip + 1][1],
                        sK + k_off[nip] + ks * 32);
            #pragma unroll
            for (int ni = 0; ni < 8; ni++) {
                mma_f16(sacc[0][ni], qa[0][0], qa[0][1], qa[0][2], qa[0][3],
                        kf[ni][0], kf[ni][1]);
                mma_f16(sacc[1][ni], qa[1][0], qa[1][1], qa[1][2], qa[1][3],
                        kf[ni][0], kf[ni][1]);
            }
        }

        // ---- causal mask on diagonal band ----
        if (jt >= 2 * bx) {
            #pragma unroll
            for (int mi = 0; mi < 2; mi++) {
                int row0 = qb + wid * 32 + mi * 16 + g;
                #pragma unroll
                for (int ni = 0; ni < 8; ni++) {
                    int col0 = jt * 64 + ni * 8 + 2 * t;
                    if (col0     > row0)     sacc[mi][ni][0] = -1e30f;
                    if (col0 + 1 > row0)     sacc[mi][ni][1] = -1e30f;
                    if (col0     > row0 + 8) sacc[mi][ni][2] = -1e30f;
                    if (col0 + 1 > row0 + 8) sacc[mi][ni][3] = -1e30f;
                }
            }
        }

        // ---- online softmax ----
        #pragma unroll
        for (int rm = 0; rm < 4; rm++) {
            const int mi = rm >> 1;
            const int c0 = (rm & 1) * 2;
            float mx = -1e30f;
            #pragma unroll
            for (int ni = 0; ni < 8; ni++)
                mx = fmaxf(mx, fmaxf(sacc[mi][ni][c0], sacc[mi][ni][c0 + 1]));
            mx = fmaxf(mx, __shfl_xor_sync(0xffffffffu, mx, 1));
            mx = fmaxf(mx, __shfl_xor_sync(0xffffffffu, mx, 2));
            float mn = fmaxf(m[rm], mx);
            float alpha = __expf(m[rm] - mn);
            float rs = 0.f;
            #pragma unroll
            for (int ni = 0; ni < 8; ni++) {
                float p0 = __expf(sacc[mi][ni][c0] - mn);
                float p1 = __expf(sacc[mi][ni][c0 + 1] - mn);
                sacc[mi][ni][c0] = p0;
                sacc[mi][ni][c0 + 1] = p1;
                rs += p0 + p1;
            }
            rs += __shfl_xor_sync(0xffffffffu, rs, 1);
            rs += __shfl_xor_sync(0xffffffffu, rs, 2);
            l[rm] = l[rm] * alpha + rs;
            m[rm] = mn;
            #pragma unroll
            for (int ni = 0; ni < 8; ni++) {
                o[mi][ni][c0] *= alpha;
                o[mi][ni][c0 + 1] *= alpha;
            }
        }

        // ---- O += P @ V : P A-frags are packed C-frags (no shuffles) ----
        #pragma unroll
        for (int js = 0; js < 4; js++) {           // k16 slices over 64 keys
            uint32_t pa[2][4];
            #pragma unroll
            for (int mi = 0; mi < 2; mi++) {
                pa[mi][0] = pack_h2(sacc[mi][2 * js][0],     sacc[mi][2 * js][1]);
                pa[mi][1] = pack_h2(sacc[mi][2 * js][2],     sacc[mi][2 * js][3]);
                pa[mi][2] = pack_h2(sacc[mi][2 * js + 1][0], sacc[mi][2 * js + 1][1]);
                pa[mi][3] = pack_h2(sacc[mi][2 * js + 1][2], sacc[mi][2 * js + 1][3]);
            }
            uint32_t vf[8][2];
            #pragma unroll
            for (int nip = 0; nip < 4; nip++)
                ldsm_x4_t(vf[2 * nip][0], vf[2 * nip][1],
                          vf[2 * nip + 1][0], vf[2 * nip + 1][1],
                          sV + js * 16 * 144 + v_off[nip]);
            #pragma unroll
            for (int ni = 0; ni < 8; ni++) {
                mma_f16(o[0][ni], pa[0][0], pa[0][1], pa[0][2], pa[0][3],
                        vf[ni][0], vf[ni][1]);
                mma_f16(o[1][ni], pa[1][0], pa[1][1], pa[1][2], pa[1][3],
                        vf[ni][0], vf[ni][1]);
            }
        }
        __syncthreads();
    }

    // ---- epilogue: y = O / l (fp16, consumed by GEMM2) ----
    __half* yb = y + (size_t)b * TSEQ * C_EMBD + h * HD;
    #pragma unroll
    for (int mi = 0; mi < 2; mi++) {
        #pragma unroll
        for (int hf = 0; hf < 2; hf++) {
            const int rm = mi * 2 + hf;
            const float inv = 1.f / l[rm];
            const int row = qb + wid * 32 + mi * 16 + hf * 8 + g;
            #pragma unroll
            for (int ni = 0; ni < 8; ni++) {
                *(uint32_t*)&yb[(size_t)row * C_EMBD + ni * 8 + 2 * t] =
                    pack_h2(o[mi][ni][hf * 2] * inv, o[mi][ni][hf * 2 + 1] * inv);
            }
        }
    }
}

// ---------------------------------------------------------------------------
extern "C" void kernel_launch(void* const* d_in, const int* in_sizes, int n_in,
                              void* d_out, int out_size)
{
    const float* x      = (const float*)d_in[0];
    const float* W_attn = (const float*)d_in[1];
    const float* b_attn = (const float*)d_in[2];
    const float* W_proj = (const float*)d_in[3];
    const float* b_proj = (const float*)d_in[4];
    float* out = (float*)d_out;

    __half *qkv, *y, *xc, *WaT, *WpT;
    cudaGetSymbolAddress((void**)&qkv, g_qkv);
    cudaGetSymbolAddress((void**)&y, g_y);
    cudaGetSymbolAddress((void**)&xc, g_xc);
    cudaGetSymbolAddress((void**)&WaT, g_WaT);
    cudaGetSymbolAddress((void**)&WpT, g_WpT);

    const int M = BATCH * TSEQ;  // 8192

    static int attr_set = 0;
    if (!attr_set) {
        cudaFuncSetAttribute(f16_gemm_kernel,
                             cudaFuncAttributeMaxDynamicSharedMemorySize, GEMM_SMEM);
        cudaFuncSetAttribute(attn_tc_kernel,
                             cudaFuncAttributeMaxDynamicSharedMemorySize, ATT_SMEM);
        attr_set = 1;
    }

    // 0) Producers: convert x to fp16; transpose+convert weights
    {
        cvt_f16_kernel<<<(M * C_EMBD) / 1024, 256>>>((const float4*)x, (uint2*)xc);
        dim3 g1(3 * C_EMBD / 32, C_EMBD / 32);
        transpose_kernel<<<g1, 256>>>(W_attn, WaT, C_EMBD, 3 * C_EMBD);
        dim3 g2(C_EMBD / 32, C_EMBD / 32);
        transpose_kernel<<<g2, 256>>>(W_proj, WpT, C_EMBD, C_EMBD);
    }

    // 1) QKV GEMM (fp16 mma, epilogue: scale q, fp16 out)
    {
        dim3 grid(3 * C_EMBD / 256, M / 128);
        f16_gemm_kernel<<<grid, 256, GEMM_SMEM>>>(xc, WaT, b_attn, qkv,
                                                  M, 3 * C_EMBD, C_EMBD, 1);
    }

    // 2) fp16 tensor-core flash attention
    {
        dim3 grid(TSEQ / 128, NH, BATCH);
        attn_tc_kernel<<<grid, 128, ATT_SMEM>>>(qkv, y);
    }

    // 3) Output projection (fp16 mma, fp32 out)
    {
        dim3 grid(C_EMBD / 256, M / 128);
        f16_gemm_kernel<<<grid, 256, GEMM_SMEM>>>(y, WpT, b_proj, out,
                                                  M, C_EMBD, C_EMBD, 0);
    }
}

// round 9
// speedup vs baseline: 8.4250x; 1.0260x over previous
#include <cuda_runtime.h>
#include <cuda_fp16.h>
#include <cstdint>
#include <math.h>

#define C_EMBD 1024
#define NH     16
#define HD     64
#define TSEQ   2048
#define BATCH  4

__device__ __half g_qkv[(size_t)BATCH * TSEQ * 3 * C_EMBD];  // fp16 (q pre-scaled)
__device__ __half g_y[(size_t)BATCH * TSEQ * C_EMBD];        // fp16
__device__ __half g_xc[(size_t)BATCH * TSEQ * C_EMBD];       // x, fp16
__device__ __half g_WaT[(size_t)3 * C_EMBD * C_EMBD];        // fp16
__device__ __half g_WpT[(size_t)C_EMBD * C_EMBD];            // fp16

// ---------------------------------------------------------------------------
// Helpers
// ---------------------------------------------------------------------------
__device__ __forceinline__ uint32_t smem_u32(const void* p) {
    uint32_t a;
    asm("{ .reg .u64 t; cvta.to.shared.u64 t, %1; cvt.u32.u64 %0, t; }" : "=r"(a) : "l"(p));
    return a;
}
__device__ __forceinline__ void cp_async16(uint32_t dst, const void* src) {
    asm volatile("cp.async.cg.shared.global [%0], [%1], 16;" :: "r"(dst), "l"(src) : "memory");
}
__device__ __forceinline__ void cp_commit() {
    asm volatile("cp.async.commit_group;" ::: "memory");
}
template <int N>
__device__ __forceinline__ void cp_wait() {
    asm volatile("cp.async.wait_group %0;" :: "n"(N) : "memory");
}
__device__ __forceinline__ uint32_t pack_h2(float a, float b) {
    __half2 h = __floats2half2_rn(a, b);
    return *(uint32_t*)&h;
}
__device__ __forceinline__ void mma_f16(float* c, uint32_t a0, uint32_t a1,
                                        uint32_t a2, uint32_t a3,
                                        uint32_t b0, uint32_t b1) {
    asm volatile(
        "mma.sync.aligned.m16n8k16.row.col.f32.f16.f16.f32 "
        "{%0,%1,%2,%3}, {%4,%5,%6,%7}, {%8,%9}, {%0,%1,%2,%3};"
        : "+f"(c[0]), "+f"(c[1]), "+f"(c[2]), "+f"(c[3])
        : "r"(a0), "r"(a1), "r"(a2), "r"(a3), "r"(b0), "r"(b1));
}
__device__ __forceinline__ void ldsm_x4(uint32_t& r0, uint32_t& r1,
                                        uint32_t& r2, uint32_t& r3, uint32_t addr) {
    asm volatile("ldmatrix.sync.aligned.m8n8.x4.shared.b16 {%0,%1,%2,%3}, [%4];"
                 : "=r"(r0), "=r"(r1), "=r"(r2), "=r"(r3) : "r"(addr));
}
__device__ __forceinline__ void ldsm_x4_t(uint32_t& r0, uint32_t& r1,
                                          uint32_t& r2, uint32_t& r3, uint32_t addr) {
    asm volatile("ldmatrix.sync.aligned.m8n8.x4.trans.shared.b16 {%0,%1,%2,%3}, [%4];"
                 : "=r"(r0), "=r"(r1), "=r"(r2), "=r"(r3) : "r"(addr));
}

// ---------------------------------------------------------------------------
// Elementwise fp16 convert (for x)
// ---------------------------------------------------------------------------
__global__ __launch_bounds__(256)
void cvt_f16_kernel(const float4* __restrict__ in, uint2* __restrict__ out)
{
    int i = blockIdx.x * 256 + threadIdx.x;
    float4 v = in[i];
    out[i] = make_uint2(pack_h2(v.x, v.y), pack_h2(v.z, v.w));
}

// ---------------------------------------------------------------------------
// Weight transpose + fp16 convert: W[R][Ncols] (f32) -> WT[Ncols][R] (f16)
// ---------------------------------------------------------------------------
__global__ __launch_bounds__(256)
void transpose_kernel(const float* __restrict__ W, __half* __restrict__ WT,
                      int R, int Ncols)
{
    __shared__ float t[32][33];
    const int bx = blockIdx.x * 32;
    const int by = blockIdx.y * 32;
    const int tx = threadIdx.x & 31;
    const int ty8 = threadIdx.x >> 5;
    #pragma unroll
    for (int i = 0; i < 32; i += 8)
        t[ty8 + i][tx] = W[(size_t)(by + ty8 + i) * Ncols + bx + tx];
    __syncthreads();
    #pragma unroll
    for (int i = 0; i < 32; i += 8)
        WT[(size_t)(bx + ty8 + i) * R + by + tx] = __float2half_rn(t[tx][ty8 + i]);
}

// ---------------------------------------------------------------------------
// fp16 mma.sync GEMM with bias: C[M,N] = A[M,K] @ BT[N,K]^T + bias[N]
// CTA tile 128x128, BK=64, 8 warps (2x4), warp tile 64x32.
// 3-stage cp.async pipeline (96 KB), TWO CTAs per SM (launch_bounds(256,2)).
// mode 0: f32 out. mode 1: f16 out, cols<C_EMBD scaled by 0.125 (q).
// ---------------------------------------------------------------------------
#define GEMM_SMEM 98304

__global__ __launch_bounds__(256, 2)
void f16_gemm_kernel(const __half* __restrict__ A,
                     const __half* __restrict__ BT,
                     const float* __restrict__ bias,
                     void* __restrict__ Cm,
                     int M, int N, int K, int mode)
{
    extern __shared__ char smem[];
    const uint32_t sb = smem_u32(smem);

    const int tid = threadIdx.x;
    const int wid = tid >> 5;
    const int lane = tid & 31;
    const int g = lane >> 2;
    const int t = lane & 3;
    const int wm = wid >> 2;      // 0..1
    const int wn = wid & 3;       // 0..3

    const int bm0 = blockIdx.y * 128;
    const int bn0 = blockIdx.x * 128;
    const int NS = K >> 6;        // BK=64

    // ldmatrix per-lane geometry
    const int a_lrow = (lane & 7) | ((lane & 8)  ? 8 : 0);
    const int a_sel  = lane >> 4;
    const int b_lrow = (lane & 7) | ((lane & 16) ? 8 : 0);
    const int b_sel  = (lane >> 3) & 1;
    uint32_t a_off[4], a_rot[4], b_off[2], b_rot[2];
    #pragma unroll
    for (int mi = 0; mi < 4; mi++) {
        int row = wm * 64 + mi * 16 + a_lrow;
        a_off[mi] = (uint32_t)row << 7;
        a_rot[mi] = row & 7;
    }
    #pragma unroll
    for (int nip = 0; nip < 2; nip++) {
        int row = wn * 32 + nip * 16 + b_lrow;
        b_off[nip] = (uint32_t)row << 7;
        b_rot[nip] = row & 7;
    }

    float acc[4][4][4];
    #pragma unroll
    for (int i = 0; i < 4; i++)
        #pragma unroll
        for (int j = 0; j < 4; j++)
            #pragma unroll
            for (int r = 0; r < 4; r++) acc[i][j][r] = 0.f;

    auto load_stage = [&](int s) {
        const int k0 = s * 64;
        const int buf = s % 3;
        const uint32_t sA = sb + buf * 16384;
        const uint32_t sB = sb + 49152 + buf * 16384;
        #pragma unroll
        for (int it = 0; it < 4; it++) {          // A: 1024 chunks of 16B
            int idx = it * 256 + tid;
            int r = idx >> 3, ck = idx & 7;
            uint32_t d = sA + r * 128 + ((((ck + r) & 7)) << 4);
            cp_async16(d, &A[(size_t)(bm0 + r) * K + k0 + ck * 8]);
        }
        #pragma unroll
        for (int it = 0; it < 4; it++) {          // B: 1024 chunks
            int idx = it * 256 + tid;
            int r = idx >> 3, ck = idx & 7;
            uint32_t d = sB + r * 128 + ((((ck + r) & 7)) << 4);
            cp_async16(d, &BT[(size_t)(bn0 + r) * K + k0 + ck * 8]);
        }
        cp_commit();
    };

    load_stage(0);
    load_stage(1);

    for (int s = 0; s < NS; s++) {
        if (s + 2 < NS) { load_stage(s + 2); cp_wait<2>(); }
        else if (s + 1 < NS) { cp_wait<1>(); }
        else { cp_wait<0>(); }
        __syncthreads();

        const int buf = s % 3;
        const uint32_t sA = sb + buf * 16384;
        const uint32_t sB = sb + 49152 + buf * 16384;

        #pragma unroll
        for (int ks = 0; ks < 4; ks++) {          // 4 x k16 slices
            const int ckA = 2 * ks + a_sel;
            const int ckB = 2 * ks + b_sel;
            uint32_t afr[4][4];
            #pragma unroll
            for (int mi = 0; mi < 4; mi++)
                ldsm_x4(afr[mi][0], afr[mi][1], afr[mi][2], afr[mi][3],
                        sA + a_off[mi] + (((ckA + a_rot[mi]) & 7) << 4));
            uint32_t bfr[4][2];
            #pragma unroll
            for (int nip = 0; nip < 2; nip++)
                ldsm_x4(bfr[2 * nip][0], bfr[2 * nip][1],
                        bfr[2 * nip + 1][0], bfr[2 * nip + 1][1],
                        sB + b_off[nip] + (((ckB + b_rot[nip]) & 7) << 4));
            #pragma unroll
            for (int mi = 0; mi < 4; mi++)
                #pragma unroll
                for (int ni = 0; ni < 4; ni++)
                    mma_f16(acc[mi][ni],
                            afr[mi][0], afr[mi][1], afr[mi][2], afr[mi][3],
                            bfr[ni][0], bfr[ni][1]);
        }
        __syncthreads();
    }

    #pragma unroll
    for (int mi = 0; mi < 4; mi++) {
        #pragma unroll
        for (int ni = 0; ni < 4; ni++) {
            int row0 = bm0 + wm * 64 + mi * 16 + g;
            int col  = bn0 + wn * 32 + ni * 8 + 2 * t;
            float bx = bias[col], by = bias[col + 1];
            float v00 = acc[mi][ni][0] + bx, v01 = acc[mi][ni][1] + by;
            float v10 = acc[mi][ni][2] + bx, v11 = acc[mi][ni][3] + by;
            if (mode == 1) {
                if (col < C_EMBD) {
                    v00 *= 0.125f; v01 *= 0.125f; v10 *= 0.125f; v11 *= 0.125f;
                }
                __half* Ch = (__half*)Cm;
                *(uint32_t*)&Ch[(size_t)row0 * N + col] = pack_h2(v00, v01);
                *(uint32_t*)&Ch[(size_t)(row0 + 8) * N + col] = pack_h2(v10, v11);
            } else {
                float* Cf = (float*)Cm;
                float2 w0 = {v00, v01}, w1 = {v10, v11};
                *(float2*)&Cf[(size_t)row0 * N + col] = w0;
                *(float2*)&Cf[(size_t)(row0 + 8) * N + col] = w1;
            }
        }
    }
}

// ---------------------------------------------------------------------------
// fp16 tensor-core flash attention, causal. (unchanged from R8)
// ---------------------------------------------------------------------------
#define ATT_SMEM 55296

__global__ __launch_bounds__(128, 1)
void attn_tc_kernel(const __half* __restrict__ qkv, __half* __restrict__ y)
{
    extern __shared__ char smc[];
    const uint32_t sb = smem_u32(smc);

    const int tid = threadIdx.x;
    const int wid = tid >> 5;
    const int lane = tid & 31;
    const int g = lane >> 2;
    const int t = lane & 3;
    const int bx = (gridDim.x - 1) - blockIdx.x;   // heavy tiles first
    const int h = blockIdx.y;
    const int b = blockIdx.z;
    const int qb = bx * 128;

    const __half* base = qkv + (size_t)b * TSEQ * (3 * C_EMBD) + h * HD;

    const int a_lrow = (lane & 7) | ((lane & 8)  ? 8 : 0);
    const int a_sel  = lane >> 4;
    const int b_lrow = (lane & 7) | ((lane & 16) ? 8 : 0);
    const int b_sel  = (lane >> 3) & 1;
    const int v_lrow = (lane & 7) | ((lane & 8) ? 8 : 0);
    const int v_c16  = (lane & 16) ? 16 : 0;

    uint32_t q_addr[2];
    #pragma unroll
    for (int mi = 0; mi < 2; mi++)
        q_addr[mi] = sb + (wid * 32 + mi * 16 + a_lrow) * 144 + a_sel * 16;
    uint32_t k_off[4];
    #pragma unroll
    for (int nip = 0; nip < 4; nip++)
        k_off[nip] = (nip * 16 + b_lrow) * 144 + b_sel * 16;
    uint32_t v_off[4];
    #pragma unroll
    for (int nip = 0; nip < 4; nip++)
        v_off[nip] = v_lrow * 144 + nip * 32 + v_c16;

    auto issue_kv = [&](int jt) {
        const uint32_t sk = sb + 18432 + (jt & 1) * 9216;
        const uint32_t sv = sb + 36864 + (jt & 1) * 9216;
        #pragma unroll
        for (int it = 0; it < 4; it++) {
            int idx = it * 128 + tid;
            int r = idx >> 3, ck = idx & 7;
            cp_async16(sk + r * 144 + ck * 16,
                       base + (size_t)(jt * 64 + r) * (3 * C_EMBD) + C_EMBD + ck * 8);
        }
        #pragma unroll
        for (int it = 0; it < 4; it++) {
            int idx = it * 128 + tid;
            int r = idx >> 3, ck = idx & 7;
            cp_async16(sv + r * 144 + ck * 16,
                       base + (size_t)(jt * 64 + r) * (3 * C_EMBD) + 2 * C_EMBD + ck * 8);
        }
    };

    #pragma unroll
    for (int it = 0; it < 8; it++) {
        int idx = it * 128 + tid;
        int r = idx >> 3, ck = idx & 7;
        cp_async16(sb + r * 144 + ck * 16,
                   base + (size_t)(qb + r) * (3 * C_EMBD) + ck * 8);
    }
    issue_kv(0);
    cp_commit();

    float m[4], l[4], o[2][8][4];
    #pragma unroll
    for (int rm = 0; rm < 4; rm++) { m[rm] = -1e30f; l[rm] = 0.f; }
    #pragma unroll
    for (int mi = 0; mi < 2; mi++)
        #pragma unroll
        for (int ni = 0; ni < 8; ni++)
            #pragma unroll
            for (int k = 0; k < 4; k++) o[mi][ni][k] = 0.f;

    const int ntiles = 2 * bx + 2;

    for (int jt = 0; jt < ntiles; jt++) {
        if (jt + 1 < ntiles) { issue_kv(jt + 1); cp_commit(); cp_wait<1>(); }
        else { cp_wait<0>(); }
        __syncthreads();

        const uint32_t sK = sb + 18432 + (jt & 1) * 9216;
        const uint32_t sV = sb + 36864 + (jt & 1) * 9216;

        float sacc[2][8][4];
        #pragma unroll
        for (int mi = 0; mi < 2; mi++)
            #pragma unroll
            for (int ni = 0; ni < 8; ni++)
                #pragma unroll
                for (int k = 0; k < 4; k++) sacc[mi][ni][k] = 0.f;

        #pragma unroll
        for (int ks = 0; ks < 4; ks++) {
            uint32_t qa[2][4];
            #pragma unroll
            for (int mi = 0; mi < 2; mi++)
                ldsm_x4(qa[mi][0], qa[mi][1], qa[mi][2], qa[mi][3],
                        q_addr[mi] + ks * 32);
            uint32_t kf[8][2];
            #pragma unroll
            for (int nip = 0; nip < 4; nip++)
                ldsm_x4(kf[2 * nip][0], kf[2 * nip][1],
                        kf[2 * nip + 1][0], kf[2 * nip + 1][1],
                        sK + k_off[nip] + ks * 32);
            #pragma unroll
            for (int ni = 0; ni < 8; ni++) {
                mma_f16(sacc[0][ni], qa[0][0], qa[0][1], qa[0][2], qa[0][3],
                        kf[ni][0], kf[ni][1]);
                mma_f16(sacc[1][ni], qa[1][0], qa[1][1], qa[1][2], qa[1][3],
                        kf[ni][0], kf[ni][1]);
            }
        }

        if (jt >= 2 * bx) {
            #pragma unroll
            for (int mi = 0; mi < 2; mi++) {
                int row0 = qb + wid * 32 + mi * 16 + g;
                #pragma unroll
                for (int ni = 0; ni < 8; ni++) {
                    int col0 = jt * 64 + ni * 8 + 2 * t;
                    if (col0     > row0)     sacc[mi][ni][0] = -1e30f;
                    if (col0 + 1 > row0)     sacc[mi][ni][1] = -1e30f;
                    if (col0     > row0 + 8) sacc[mi][ni][2] = -1e30f;
                    if (col0 + 1 > row0 + 8) sacc[mi][ni][3] = -1e30f;
                }
            }
        }

        #pragma unroll
        for (int rm = 0; rm < 4; rm++) {
            const int mi = rm >> 1;
            const int c0 = (rm & 1) * 2;
            float mx = -1e30f;
            #pragma unroll
            for (int ni = 0; ni < 8; ni++)
                mx = fmaxf(mx, fmaxf(sacc[mi][ni][c0], sacc[mi][ni][c0 + 1]));
            mx = fmaxf(mx, __shfl_xor_sync(0xffffffffu, mx, 1));
            mx = fmaxf(mx, __shfl_xor_sync(0xffffffffu, mx, 2));
            float mn = fmaxf(m[rm], mx);
            float alpha = __expf(m[rm] - mn);
            float rs = 0.f;
            #pragma unroll
            for (int ni = 0; ni < 8; ni++) {
                float p0 = __expf(sacc[mi][ni][c0] - mn);
                float p1 = __expf(sacc[mi][ni][c0 + 1] - mn);
                sacc[mi][ni][c0] = p0;
                sacc[mi][ni][c0 + 1] = p1;
                rs += p0 + p1;
            }
            rs += __shfl_xor_sync(0xffffffffu, rs, 1);
            rs += __shfl_xor_sync(0xffffffffu, rs, 2);
            l[rm] = l[rm] * alpha + rs;
            m[rm] = mn;
            #pragma unroll
            for (int ni = 0; ni < 8; ni++) {
                o[mi][ni][c0] *= alpha;
                o[mi][ni][c0 + 1] *= alpha;
            }
        }

        #pragma unroll
        for (int js = 0; js < 4; js++) {
            uint32_t pa[2][4];
            #pragma unroll
            for (int mi = 0; mi < 2; mi++) {
                pa[mi][0] = pack_h2(sacc[mi][2 * js][0],     sacc[mi][2 * js][1]);
                pa[mi][1] = pack_h2(sacc[mi][2 * js][2],     sacc[mi][2 * js][3]);
                pa[mi][2] = pack_h2(sacc[mi][2 * js + 1][0], sacc[mi][2 * js + 1][1]);
                pa[mi][3] = pack_h2(sacc[mi][2 * js + 1][2], sacc[mi][2 * js + 1][3]);
            }
            uint32_t vf[8][2];
            #pragma unroll
            for (int nip = 0; nip < 4; nip++)
                ldsm_x4_t(vf[2 * nip][0], vf[2 * nip][1],
                          vf[2 * nip + 1][0], vf[2 * nip + 1][1],
                          sV + js * 16 * 144 + v_off[nip]);
            #pragma unroll
            for (int ni = 0; ni < 8; ni++) {
                mma_f16(o[0][ni], pa[0][0], pa[0][1], pa[0][2], pa[0][3],
                        vf[ni][0], vf[ni][1]);
                mma_f16(o[1][ni], pa[1][0], pa[1][1], pa[1][2], pa[1][3],
                        vf[ni][0], vf[ni][1]);
            }
        }
        __syncthreads();
    }

    __half* yb = y + (size_t)b * TSEQ * C_EMBD + h * HD;
    #pragma unroll
    for (int mi = 0; mi < 2; mi++) {
        #pragma unroll
        for (int hf = 0; hf < 2; hf++) {
            const int rm = mi * 2 + hf;
            const float inv = 1.f / l[rm];
            const int row = qb + wid * 32 + mi * 16 + hf * 8 + g;
            #pragma unroll
            for (int ni = 0; ni < 8; ni++) {
                *(uint32_t*)&yb[(size_t)row * C_EMBD + ni * 8 + 2 * t] =
                    pack_h2(o[mi][ni][hf * 2] * inv, o[mi][ni][hf * 2 + 1] * inv);
            }
        }
    }
}

// ---------------------------------------------------------------------------
extern "C" void kernel_launch(void* const* d_in, const int* in_sizes, int n_in,
                              void* d_out, int out_size)
{
    const float* x      = (const float*)d_in[0];
    const float* W_attn = (const float*)d_in[1];
    const float* b_attn = (const float*)d_in[2];
    const float* W_proj = (const float*)d_in[3];
    const float* b_proj = (const float*)d_in[4];
    float* out = (float*)d_out;

    __half *qkv, *y, *xc, *WaT, *WpT;
    cudaGetSymbolAddress((void**)&qkv, g_qkv);
    cudaGetSymbolAddress((void**)&y, g_y);
    cudaGetSymbolAddress((void**)&xc, g_xc);
    cudaGetSymbolAddress((void**)&WaT, g_WaT);
    cudaGetSymbolAddress((void**)&WpT, g_WpT);

    const int M = BATCH * TSEQ;  // 8192

    static int attr_set = 0;
    if (!attr_set) {
        cudaFuncSetAttribute(f16_gemm_kernel,
                             cudaFuncAttributeMaxDynamicSharedMemorySize, GEMM_SMEM);
        cudaFuncSetAttribute(attn_tc_kernel,
                             cudaFuncAttributeMaxDynamicSharedMemorySize, ATT_SMEM);
        attr_set = 1;
    }

    // 0) Producers: convert x to fp16; transpose+convert weights
    {
        cvt_f16_kernel<<<(M * C_EMBD) / 1024, 256>>>((const float4*)x, (uint2*)xc);
        dim3 g1(3 * C_EMBD / 32, C_EMBD / 32);
        transpose_kernel<<<g1, 256>>>(W_attn, WaT, C_EMBD, 3 * C_EMBD);
        dim3 g2(C_EMBD / 32, C_EMBD / 32);
        transpose_kernel<<<g2, 256>>>(W_proj, WpT, C_EMBD, C_EMBD);
    }

    // 1) QKV GEMM (fp16 mma, epilogue: scale q, fp16 out)
    {
        dim3 grid(3 * C_EMBD / 128, M / 128);
        f16_gemm_kernel<<<grid, 256, GEMM_SMEM>>>(xc, WaT, b_attn, qkv,
                                                  M, 3 * C_EMBD, C_EMBD, 1);
    }

    // 2) fp16 tensor-core flash attention
    {
        dim3 grid(TSEQ / 128, NH, BATCH);
        attn_tc_kernel<<<grid, 128, ATT_SMEM>>>(qkv, y);
    }

    // 3) Output projection (fp16 mma, fp32 out)
    {
        dim3 grid(C_EMBD / 128, M / 128);
        f16_gemm_kernel<<<grid, 256, GEMM_SMEM>>>(y, WpT, b_proj, out,
                                                  M, C_EMBD, C_EMBD, 0);
    }
}

// round 10
// speedup vs baseline: 8.4717x; 1.0055x over previous
#include <cuda_runtime.h>
#include <cuda_fp16.h>
#include <cstdint>
#include <math.h>

#define C_EMBD 1024
#define NH     16
#define HD     64
#define TSEQ   2048
#define BATCH  4

__device__ __half g_qkv[(size_t)BATCH * TSEQ * 3 * C_EMBD];  // fp16 (q pre-scaled)
__device__ __half g_y[(size_t)BATCH * TSEQ * C_EMBD];        // fp16
__device__ __half g_xc[(size_t)BATCH * TSEQ * C_EMBD];       // x, fp16
__device__ __half g_WaT[(size_t)3 * C_EMBD * C_EMBD];        // fp16
__device__ __half g_WpT[(size_t)C_EMBD * C_EMBD];            // fp16

// ---------------------------------------------------------------------------
// Helpers
// ---------------------------------------------------------------------------
__device__ __forceinline__ uint32_t smem_u32(const void* p) {
    uint32_t a;
    asm("{ .reg .u64 t; cvta.to.shared.u64 t, %1; cvt.u32.u64 %0, t; }" : "=r"(a) : "l"(p));
    return a;
}
__device__ __forceinline__ void cp_async16(uint32_t dst, const void* src) {
    asm volatile("cp.async.cg.shared.global [%0], [%1], 16;" :: "r"(dst), "l"(src) : "memory");
}
__device__ __forceinline__ void cp_commit() {
    asm volatile("cp.async.commit_group;" ::: "memory");
}
template <int N>
__device__ __forceinline__ void cp_wait() {
    asm volatile("cp.async.wait_group %0;" :: "n"(N) : "memory");
}
__device__ __forceinline__ uint32_t pack_h2(float a, float b) {
    __half2 h = __floats2half2_rn(a, b);
    return *(uint32_t*)&h;
}
__device__ __forceinline__ void mma_f16(float* c, uint32_t a0, uint32_t a1,
                                        uint32_t a2, uint32_t a3,
                                        uint32_t b0, uint32_t b1) {
    asm volatile(
        "mma.sync.aligned.m16n8k16.row.col.f32.f16.f16.f32 "
        "{%0,%1,%2,%3}, {%4,%5,%6,%7}, {%8,%9}, {%0,%1,%2,%3};"
        : "+f"(c[0]), "+f"(c[1]), "+f"(c[2]), "+f"(c[3])
        : "r"(a0), "r"(a1), "r"(a2), "r"(a3), "r"(b0), "r"(b1));
}
__device__ __forceinline__ void ldsm_x4(uint32_t& r0, uint32_t& r1,
                                        uint32_t& r2, uint32_t& r3, uint32_t addr) {
    asm volatile("ldmatrix.sync.aligned.m8n8.x4.shared.b16 {%0,%1,%2,%3}, [%4];"
                 : "=r"(r0), "=r"(r1), "=r"(r2), "=r"(r3) : "r"(addr));
}
__device__ __forceinline__ void ldsm_x4_t(uint32_t& r0, uint32_t& r1,
                                          uint32_t& r2, uint32_t& r3, uint32_t addr) {
    asm volatile("ldmatrix.sync.aligned.m8n8.x4.trans.shared.b16 {%0,%1,%2,%3}, [%4];"
                 : "=r"(r0), "=r"(r1), "=r"(r2), "=r"(r3) : "r"(addr));
}

// ---------------------------------------------------------------------------
// Elementwise fp16 convert (for x)
// ---------------------------------------------------------------------------
__global__ __launch_bounds__(256)
void cvt_f16_kernel(const float4* __restrict__ in, uint2* __restrict__ out)
{
    int i = blockIdx.x * 256 + threadIdx.x;
    float4 v = in[i];
    out[i] = make_uint2(pack_h2(v.x, v.y), pack_h2(v.z, v.w));
}

// ---------------------------------------------------------------------------
// Weight transpose + fp16 convert: W[R][Ncols] (f32) -> WT[Ncols][R] (f16)
// ---------------------------------------------------------------------------
__global__ __launch_bounds__(256)
void transpose_kernel(const float* __restrict__ W, __half* __restrict__ WT,
                      int R, int Ncols)
{
    __shared__ float t[32][33];
    const int bx = blockIdx.x * 32;
    const int by = blockIdx.y * 32;
    const int tx = threadIdx.x & 31;
    const int ty8 = threadIdx.x >> 5;
    #pragma unroll
    for (int i = 0; i < 32; i += 8)
        t[ty8 + i][tx] = W[(size_t)(by + ty8 + i) * Ncols + bx + tx];
    __syncthreads();
    #pragma unroll
    for (int i = 0; i < 32; i += 8)
        WT[(size_t)(bx + ty8 + i) * R + by + tx] = __float2half_rn(t[tx][ty8 + i]);
}

// ---------------------------------------------------------------------------
// fp16 mma.sync GEMM with bias: C[M,N] = A[M,K] @ BT[N,K]^T + bias[N]
// CTA tile 128x128, BK=64, 4 warps (2x2), warp tile 64x64 (ratio 4 MMA/LDSM).
// 3-stage cp.async pipeline (96 KB), 2 CTAs/SM (launch_bounds(128,2)).
// mode 0: f32 out. mode 1: f16 out, cols<C_EMBD scaled by 0.125 (q).
// ---------------------------------------------------------------------------
#define GEMM_SMEM 98304

__global__ __launch_bounds__(128, 2)
void f16_gemm_kernel(const __half* __restrict__ A,
                     const __half* __restrict__ BT,
                     const float* __restrict__ bias,
                     void* __restrict__ Cm,
                     int M, int N, int K, int mode)
{
    extern __shared__ char smem[];
    const uint32_t sb = smem_u32(smem);

    const int tid = threadIdx.x;
    const int wid = tid >> 5;
    const int lane = tid & 31;
    const int g = lane >> 2;
    const int t = lane & 3;
    const int wm = wid >> 1;      // 0..1
    const int wn = wid & 1;       // 0..1

    const int bm0 = blockIdx.y * 128;
    const int bn0 = blockIdx.x * 128;
    const int NS = K >> 6;        // BK=64

    // ldmatrix per-lane geometry
    const int a_lrow = (lane & 7) | ((lane & 8)  ? 8 : 0);
    const int a_sel  = lane >> 4;
    const int b_lrow = (lane & 7) | ((lane & 16) ? 8 : 0);
    const int b_sel  = (lane >> 3) & 1;
    uint32_t a_off[4], a_rot[4], b_off[4], b_rot[4];
    #pragma unroll
    for (int mi = 0; mi < 4; mi++) {
        int row = wm * 64 + mi * 16 + a_lrow;
        a_off[mi] = (uint32_t)row << 7;
        a_rot[mi] = row & 7;
    }
    #pragma unroll
    for (int nip = 0; nip < 4; nip++) {
        int row = wn * 64 + nip * 16 + b_lrow;
        b_off[nip] = (uint32_t)row << 7;
        b_rot[nip] = row & 7;
    }

    float acc[4][8][4];
    #pragma unroll
    for (int i = 0; i < 4; i++)
        #pragma unroll
        for (int j = 0; j < 8; j++)
            #pragma unroll
            for (int r = 0; r < 4; r++) acc[i][j][r] = 0.f;

    auto load_stage = [&](int s) {
        const int k0 = s * 64;
        const int buf = s % 3;
        const uint32_t sA = sb + buf * 16384;
        const uint32_t sB = sb + 49152 + buf * 16384;
        #pragma unroll
        for (int it = 0; it < 8; it++) {          // A: 1024 chunks of 16B
            int idx = it * 128 + tid;
            int r = idx >> 3, ck = idx & 7;
            uint32_t d = sA + r * 128 + ((((ck + r) & 7)) << 4);
            cp_async16(d, &A[(size_t)(bm0 + r) * K + k0 + ck * 8]);
        }
        #pragma unroll
        for (int it = 0; it < 8; it++) {          // B: 1024 chunks
            int idx = it * 128 + tid;
            int r = idx >> 3, ck = idx & 7;
            uint32_t d = sB + r * 128 + ((((ck + r) & 7)) << 4);
            cp_async16(d, &BT[(size_t)(bn0 + r) * K + k0 + ck * 8]);
        }
        cp_commit();
    };

    load_stage(0);
    load_stage(1);

    for (int s = 0; s < NS; s++) {
        if (s + 2 < NS) { load_stage(s + 2); cp_wait<2>(); }
        else if (s + 1 < NS) { cp_wait<1>(); }
        else { cp_wait<0>(); }
        __syncthreads();

        const int buf = s % 3;
        const uint32_t sA = sb + buf * 16384;
        const uint32_t sB = sb + 49152 + buf * 16384;

        #pragma unroll
        for (int ks = 0; ks < 4; ks++) {          // 4 x k16 slices
            const int ckA = 2 * ks + a_sel;
            const int ckB = 2 * ks + b_sel;
            uint32_t afr[4][4];
            #pragma unroll
            for (int mi = 0; mi < 4; mi++)
                ldsm_x4(afr[mi][0], afr[mi][1], afr[mi][2], afr[mi][3],
                        sA + a_off[mi] + (((ckA + a_rot[mi]) & 7) << 4));
            uint32_t bfr[8][2];
            #pragma unroll
            for (int nip = 0; nip < 4; nip++)
                ldsm_x4(bfr[2 * nip][0], bfr[2 * nip][1],
                        bfr[2 * nip + 1][0], bfr[2 * nip + 1][1],
                        sB + b_off[nip] + (((ckB + b_rot[nip]) & 7) << 4));
            #pragma unroll
            for (int mi = 0; mi < 4; mi++)
                #pragma unroll
                for (int ni = 0; ni < 8; ni++)
                    mma_f16(acc[mi][ni],
                            afr[mi][0], afr[mi][1], afr[mi][2], afr[mi][3],
                            bfr[ni][0], bfr[ni][1]);
        }
        __syncthreads();
    }

    #pragma unroll
    for (int mi = 0; mi < 4; mi++) {
        #pragma unroll
        for (int ni = 0; ni < 8; ni++) {
            int row0 = bm0 + wm * 64 + mi * 16 + g;
            int col  = bn0 + wn * 64 + ni * 8 + 2 * t;
            float bx = bias[col], by = bias[col + 1];
            float v00 = acc[mi][ni][0] + bx, v01 = acc[mi][ni][1] + by;
            float v10 = acc[mi][ni][2] + bx, v11 = acc[mi][ni][3] + by;
            if (mode == 1) {
                if (col < C_EMBD) {
                    v00 *= 0.125f; v01 *= 0.125f; v10 *= 0.125f; v11 *= 0.125f;
                }
                __half* Ch = (__half*)Cm;
                *(uint32_t*)&Ch[(size_t)row0 * N + col] = pack_h2(v00, v01);
                *(uint32_t*)&Ch[(size_t)(row0 + 8) * N + col] = pack_h2(v10, v11);
            } else {
                float* Cf = (float*)Cm;
                float2 w0 = {v00, v01}, w1 = {v10, v11};
                *(float2*)&Cf[(size_t)row0 * N + col] = w0;
                *(float2*)&Cf[(size_t)(row0 + 8) * N + col] = w1;
            }
        }
    }
}

// ---------------------------------------------------------------------------
// fp16 tensor-core flash attention, causal. Now 2 CTAs/SM.
// ---------------------------------------------------------------------------
#define ATT_SMEM 55296

__global__ __launch_bounds__(128, 2)
void attn_tc_kernel(const __half* __restrict__ qkv, __half* __restrict__ y)
{
    extern __shared__ char smc[];
    const uint32_t sb = smem_u32(smc);

    const int tid = threadIdx.x;
    const int wid = tid >> 5;
    const int lane = tid & 31;
    const int g = lane >> 2;
    const int t = lane & 3;
    const int bx = (gridDim.x - 1) - blockIdx.x;   // heavy tiles first
    const int h = blockIdx.y;
    const int b = blockIdx.z;
    const int qb = bx * 128;

    const __half* base = qkv + (size_t)b * TSEQ * (3 * C_EMBD) + h * HD;

    const int a_lrow = (lane & 7) | ((lane & 8)  ? 8 : 0);
    const int a_sel  = lane >> 4;
    const int b_lrow = (lane & 7) | ((lane & 16) ? 8 : 0);
    const int b_sel  = (lane >> 3) & 1;
    const int v_lrow = (lane & 7) | ((lane & 8) ? 8 : 0);
    const int v_c16  = (lane & 16) ? 16 : 0;

    uint32_t q_addr[2];
    #pragma unroll
    for (int mi = 0; mi < 2; mi++)
        q_addr[mi] = sb + (wid * 32 + mi * 16 + a_lrow) * 144 + a_sel * 16;
    uint32_t k_off[4];
    #pragma unroll
    for (int nip = 0; nip < 4; nip++)
        k_off[nip] = (nip * 16 + b_lrow) * 144 + b_sel * 16;
    uint32_t v_off[4];
    #pragma unroll
    for (int nip = 0; nip < 4; nip++)
        v_off[nip] = v_lrow * 144 + nip * 32 + v_c16;

    auto issue_kv = [&](int jt) {
        const uint32_t sk = sb + 18432 + (jt & 1) * 9216;
        const uint32_t sv = sb + 36864 + (jt & 1) * 9216;
        #pragma unroll
        for (int it = 0; it < 4; it++) {
            int idx = it * 128 + tid;
            int r = idx >> 3, ck = idx & 7;
            cp_async16(sk + r * 144 + ck * 16,
                       base + (size_t)(jt * 64 + r) * (3 * C_EMBD) + C_EMBD + ck * 8);
        }
        #pragma unroll
        for (int it = 0; it < 4; it++) {
            int idx = it * 128 + tid;
            int r = idx >> 3, ck = idx & 7;
            cp_async16(sv + r * 144 + ck * 16,
                       base + (size_t)(jt * 64 + r) * (3 * C_EMBD) + 2 * C_EMBD + ck * 8);
        }
    };

    #pragma unroll
    for (int it = 0; it < 8; it++) {
        int idx = it * 128 + tid;
        int r = idx >> 3, ck = idx & 7;
        cp_async16(sb + r * 144 + ck * 16,
                   base + (size_t)(qb + r) * (3 * C_EMBD) + ck * 8);
    }
    issue_kv(0);
    cp_commit();

    float m[4], l[4], o[2][8][4];
    #pragma unroll
    for (int rm = 0; rm < 4; rm++) { m[rm] = -1e30f; l[rm] = 0.f; }
    #pragma unroll
    for (int mi = 0; mi < 2; mi++)
        #pragma unroll
        for (int ni = 0; ni < 8; ni++)
            #pragma unroll
            for (int k = 0; k < 4; k++) o[mi][ni][k] = 0.f;

    const int ntiles = 2 * bx + 2;

    for (int jt = 0; jt < ntiles; jt++) {
        if (jt + 1 < ntiles) { issue_kv(jt + 1); cp_commit(); cp_wait<1>(); }
        else { cp_wait<0>(); }
        __syncthreads();

        const uint32_t sK = sb + 18432 + (jt & 1) * 9216;
        const uint32_t sV = sb + 36864 + (jt & 1) * 9216;

        float sacc[2][8][4];
        #pragma unroll
        for (int mi = 0; mi < 2; mi++)
            #pragma unroll
            for (int ni = 0; ni < 8; ni++)
                #pragma unroll
                for (int k = 0; k < 4; k++) sacc[mi][ni][k] = 0.f;

        #pragma unroll
        for (int ks = 0; ks < 4; ks++) {
            uint32_t qa[2][4];
            #pragma unroll
            for (int mi = 0; mi < 2; mi++)
                ldsm_x4(qa[mi][0], qa[mi][1], qa[mi][2], qa[mi][3],
                        q_addr[mi] + ks * 32);
            uint32_t kf[8][2];
            #pragma unroll
            for (int nip = 0; nip < 4; nip++)
                ldsm_x4(kf[2 * nip][0], kf[2 * nip][1],
                        kf[2 * nip + 1][0], kf[2 * nip + 1][1],
                        sK + k_off[nip] + ks * 32);
            #pragma unroll
            for (int ni = 0; ni < 8; ni++) {
                mma_f16(sacc[0][ni], qa[0][0], qa[0][1], qa[0][2], qa[0][3],
                        kf[ni][0], kf[ni][1]);
                mma_f16(sacc[1][ni], qa[1][0], qa[1][1], qa[1][2], qa[1][3],
                        kf[ni][0], kf[ni][1]);
            }
        }

        if (jt >= 2 * bx) {
            #pragma unroll
            for (int mi = 0; mi < 2; mi++) {
                int row0 = qb + wid * 32 + mi * 16 + g;
                #pragma unroll
                for (int ni = 0; ni < 8; ni++) {
                    int col0 = jt * 64 + ni * 8 + 2 * t;
                    if (col0     > row0)     sacc[mi][ni][0] = -1e30f;
                    if (col0 + 1 > row0)     sacc[mi][ni][1] = -1e30f;
                    if (col0     > row0 + 8) sacc[mi][ni][2] = -1e30f;
                    if (col0 + 1 > row0 + 8) sacc[mi][ni][3] = -1e30f;
                }
            }
        }

        #pragma unroll
        for (int rm = 0; rm < 4; rm++) {
            const int mi = rm >> 1;
            const int c0 = (rm & 1) * 2;
            float mx = -1e30f;
            #pragma unroll
            for (int ni = 0; ni < 8; ni++)
                mx = fmaxf(mx, fmaxf(sacc[mi][ni][c0], sacc[mi][ni][c0 + 1]));
            mx = fmaxf(mx, __shfl_xor_sync(0xffffffffu, mx, 1));
            mx = fmaxf(mx, __shfl_xor_sync(0xffffffffu, mx, 2));
            float mn = fmaxf(m[rm], mx);
            float alpha = __expf(m[rm] - mn);
            float rs = 0.f;
            #pragma unroll
            for (int ni = 0; ni < 8; ni++) {
                float p0 = __expf(sacc[mi][ni][c0] - mn);
                float p1 = __expf(sacc[mi][ni][c0 + 1] - mn);
                sacc[mi][ni][c0] = p0;
                sacc[mi][ni][c0 + 1] = p1;
                rs += p0 + p1;
            }
            rs += __shfl_xor_sync(0xffffffffu, rs, 1);
            rs += __shfl_xor_sync(0xffffffffu, rs, 2);
            l[rm] = l[rm] * alpha + rs;
            m[rm] = mn;
            #pragma unroll
            for (int ni = 0; ni < 8; ni++) {
                o[mi][ni][c0] *= alpha;
                o[mi][ni][c0 + 1] *= alpha;
            }
        }

        #pragma unroll
        for (int js = 0; js < 4; js++) {
            uint32_t pa[2][4];
            #pragma unroll
            for (int mi = 0; mi < 2; mi++) {
                pa[mi][0] = pack_h2(sacc[mi][2 * js][0],     sacc[mi][2 * js][1]);
                pa[mi][1] = pack_h2(sacc[mi][2 * js][2],     sacc[mi][2 * js][3]);
                pa[mi][2] = pack_h2(sacc[mi][2 * js + 1][0], sacc[mi][2 * js + 1][1]);
                pa[mi][3] = pack_h2(sacc[mi][2 * js + 1][2], sacc[mi][2 * js + 1][3]);
            }
            uint32_t vf[8][2];
            #pragma unroll
            for (int nip = 0; nip < 4; nip++)
                ldsm_x4_t(vf[2 * nip][0], vf[2 * nip][1],
                          vf[2 * nip + 1][0], vf[2 * nip + 1][1],
                          sV + js * 16 * 144 + v_off[nip]);
            #pragma unroll
            for (int ni = 0; ni < 8; ni++) {
                mma_f16(o[0][ni], pa[0][0], pa[0][1], pa[0][2], pa[0][3],
                        vf[ni][0], vf[ni][1]);
                mma_f16(o[1][ni], pa[1][0], pa[1][1], pa[1][2], pa[1][3],
                        vf[ni][0], vf[ni][1]);
            }
        }
        __syncthreads();
    }

    __half* yb = y + (size_t)b * TSEQ * C_EMBD + h * HD;
    #pragma unroll
    for (int mi = 0; mi < 2; mi++) {
        #pragma unroll
        for (int hf = 0; hf < 2; hf++) {
            const int rm = mi * 2 + hf;
            const float inv = 1.f / l[rm];
            const int row = qb + wid * 32 + mi * 16 + hf * 8 + g;
            #pragma unroll
            for (int ni = 0; ni < 8; ni++) {
                *(uint32_t*)&yb[(size_t)row * C_EMBD + ni * 8 + 2 * t] =
                    pack_h2(o[mi][ni][hf * 2] * inv, o[mi][ni][hf * 2 + 1] * inv);
            }
        }
    }
}

// ---------------------------------------------------------------------------
extern "C" void kernel_launch(void* const* d_in, const int* in_sizes, int n_in,
                              void* d_out, int out_size)
{
    const float* x      = (const float*)d_in[0];
    const float* W_attn = (const float*)d_in[1];
    const float* b_attn = (const float*)d_in[2];
    const float* W_proj = (const float*)d_in[3];
    const float* b_proj = (const float*)d_in[4];
    float* out = (float*)d_out;

    __half *qkv, *y, *xc, *WaT, *WpT;
    cudaGetSymbolAddress((void**)&qkv, g_qkv);
    cudaGetSymbolAddress((void**)&y, g_y);
    cudaGetSymbolAddress((void**)&xc, g_xc);
    cudaGetSymbolAddress((void**)&WaT, g_WaT);
    cudaGetSymbolAddress((void**)&WpT, g_WpT);

    const int M = BATCH * TSEQ;  // 8192

    static int attr_set = 0;
    if (!attr_set) {
        cudaFuncSetAttribute(f16_gemm_kernel,
                             cudaFuncAttributeMaxDynamicSharedMemorySize, GEMM_SMEM);
        cudaFuncSetAttribute(attn_tc_kernel,
                             cudaFuncAttributeMaxDynamicSharedMemorySize, ATT_SMEM);
        attr_set = 1;
    }

    // 0) Producers: convert x to fp16; transpose+convert weights
    {
        cvt_f16_kernel<<<(M * C_EMBD) / 1024, 256>>>((const float4*)x, (uint2*)xc);
        dim3 g1(3 * C_EMBD / 32, C_EMBD / 32);
        transpose_kernel<<<g1, 256>>>(W_attn, WaT, C_EMBD, 3 * C_EMBD);
        dim3 g2(C_EMBD / 32, C_EMBD / 32);
        transpose_kernel<<<g2, 256>>>(W_proj, WpT, C_EMBD, C_EMBD);
    }

    // 1) QKV GEMM (fp16 mma, epilogue: scale q, fp16 out)
    {
        dim3 grid(3 * C_EMBD / 128, M / 128);
        f16_gemm_kernel<<<grid, 128, GEMM_SMEM>>>(xc, WaT, b_attn, qkv,
                                                  M, 3 * C_EMBD, C_EMBD, 1);
    }

    // 2) fp16 tensor-core flash attention (2 CTAs/SM)
    {
        dim3 grid(TSEQ / 128, NH, BATCH);
        attn_tc_kernel<<<grid, 128, ATT_SMEM>>>(qkv, y);
    }

    // 3) Output projection (fp16 mma, fp32 out)
    {
        dim3 grid(C_EMBD / 128, M / 128);
        f16_gemm_kernel<<<grid, 128, GEMM_SMEM>>>(y, WpT, b_proj, out,
                                                  M, C_EMBD, C_EMBD, 0);
    }
}